// round 14
// baseline (speedup 1.0000x reference)
#include <cuda_runtime.h>
#include <cuda_bf16.h>
#include <math.h>
#include <stdint.h>

#define Bq 2
#define Lq 1024
#define Dq 1024
#define Hq 16
#define DKq 64
#define CHUNK 128
#define NC (Lq/CHUNK)   /* 8 */

typedef unsigned long long u64;

// ---------------- helpers ----------------
__device__ __forceinline__ uint32_t smem_u32(const void* p) {
    uint32_t a;
    asm("{ .reg .u64 t; cvta.to.shared.u64 t, %1; cvt.u32.u64 %0, t; }" : "=r"(a) : "l"(p));
    return a;
}
__device__ __forceinline__ void ldmx4(uint32_t* r, uint32_t addr) {
    asm volatile("ldmatrix.sync.aligned.m8n8.x4.shared.b16 {%0,%1,%2,%3}, [%4];"
        : "=r"(r[0]), "=r"(r[1]), "=r"(r[2]), "=r"(r[3]) : "r"(addr));
}
__device__ __forceinline__ void mma16816(float* c, const uint32_t* a, uint32_t b0, uint32_t b1) {
    asm volatile("mma.sync.aligned.m16n8k16.row.col.f32.bf16.bf16.f32 "
        "{%0,%1,%2,%3}, {%4,%5,%6,%7}, {%8,%9}, {%0,%1,%2,%3};"
        : "+f"(c[0]), "+f"(c[1]), "+f"(c[2]), "+f"(c[3])
        : "r"(a[0]), "r"(a[1]), "r"(a[2]), "r"(a[3]), "r"(b0), "r"(b1));
}
__device__ __forceinline__ uint32_t cvt2bf(float lo, float hi) {
    uint32_t r;
    asm("cvt.rn.bf16x2.f32 %0, %1, %2;" : "=r"(r) : "f"(hi), "f"(lo));
    return r;
}
__device__ __forceinline__ float tobf_f(float v) {
    return __bfloat162float(__float2bfloat16_rn(v));
}
__device__ __forceinline__ void cpa16(uint32_t saddr, const void* g) {
    asm volatile("cp.async.ca.shared.global [%0], [%1], 16;" :: "r"(saddr), "l"(g));
}
#define CPA_COMMIT() asm volatile("cp.async.commit_group;" ::: "memory")
#define CPA_WAIT2()  asm volatile("cp.async.wait_group 2;" ::: "memory")
#define CPA_WAIT1()  asm volatile("cp.async.wait_group 1;" ::: "memory")
#define CPA_WAIT0()  asm volatile("cp.async.wait_group 0;" ::: "memory")

// f32x2 packed math
__device__ __forceinline__ u64 pk2(float lo, float hi) {
    u64 r; asm("mov.b64 %0, {%1, %2};" : "=l"(r) : "f"(lo), "f"(hi)); return r;
}
__device__ __forceinline__ u64 dup2(float v) { return pk2(v, v); }
__device__ __forceinline__ void upk2(u64 x, float& lo, float& hi) {
    asm("mov.b64 {%0, %1}, %2;" : "=f"(lo), "=f"(hi) : "l"(x));
}
__device__ __forceinline__ u64 fma2(u64 a, u64 b, u64 c) {
    u64 d; asm("fma.rn.f32x2 %0, %1, %2, %3;" : "=l"(d) : "l"(a), "l"(b), "l"(c)); return d;
}
__device__ __forceinline__ u64 mul2(u64 a, u64 b) {
    u64 d; asm("mul.rn.f32x2 %0, %1, %2;" : "=l"(d) : "l"(a), "l"(b)); return d;
}
__device__ __forceinline__ u64 add2(u64 a, u64 b) {
    u64 d; asm("add.rn.f32x2 %0, %1, %2;" : "=l"(d) : "l"(a), "l"(b)); return d;
}

// pack 16 floats -> 8 bf16x2 hi + 8 bf16x2 lo
__device__ __forceinline__ void pack_split16(const float* f, uint32_t* rh, uint32_t* rl) {
#pragma unroll
    for (int j = 0; j < 8; j++) {
        float a = f[2*j], b = f[2*j+1];
        uint32_t p = cvt2bf(a, b);
        float ah = __uint_as_float(p << 16);
        float bh = __uint_as_float(p & 0xffff0000u);
        rh[j] = p;
        rl[j] = cvt2bf(a - ah, b - bh);
    }
}

// ---------------- scratch ----------------
__device__ float g_qkv  [Bq*Lq*3*Dq];
__device__ float g_kn   [Bq*Lq*Dq];
__device__ float g_so   [Bq*Lq*Dq];
__device__ float g_ys   [Bq*Lq*Dq];
__device__ __nv_bfloat16 g_xh   [Bq*Lq*Dq];
__device__ __nv_bfloat16 g_xl   [Bq*Lq*Dq];
__device__ __nv_bfloat16 g_ymh  [Bq*Lq*Dq];
__device__ __nv_bfloat16 g_yml  [Bq*Lq*Dq];
__device__ __nv_bfloat16 g_wqh  [3*Dq*Dq];
__device__ __nv_bfloat16 g_wql  [3*Dq*Dq];
__device__ __nv_bfloat16 g_woh  [Dq*Dq];
__device__ __nv_bfloat16 g_wol  [Dq*Dq];
__device__ __nv_bfloat16 g_qh [Bq*Hq*Lq*DKq];
__device__ __nv_bfloat16 g_ql [Bq*Hq*Lq*DKq];
__device__ __nv_bfloat16 g_kh [Bq*Hq*Lq*DKq];
__device__ __nv_bfloat16 g_kl [Bq*Hq*Lq*DKq];
__device__ __nv_bfloat16 g_vth[Bq*Hq*DKq*Lq];
__device__ __nv_bfloat16 g_vtl[Bq*Hq*DKq*Lq];
__device__ float g_ret  [Hq*DKq*DKq];
__device__ float g_coef [Hq*DKq*DKq];
__device__ float g_retC [Hq*DKq*DKq];
__device__ float g_A    [Bq*Hq*NC*DKq*DKq];
__device__ float g_Fin  [Bq*Hq*NC*DKq*DKq];

// ---------------- prep: plain bf16 hi/lo split (for x) ----------------
__global__ __launch_bounds__(256) void split_plain(const float* __restrict__ s,
                                                   __nv_bfloat16* __restrict__ dh,
                                                   __nv_bfloat16* __restrict__ dl, int n) {
    int i = blockIdx.x * 1024 + threadIdx.x * 4;
    if (i >= n) return;
    float4 v = *(const float4*)&s[i];
    float vs[4] = {v.x, v.y, v.z, v.w};
#pragma unroll
    for (int j = 0; j < 4; j++) {
        __nv_bfloat16 h = __float2bfloat16_rn(vs[j]);
        dh[i + j] = h;
        dl[i + j] = __float2bfloat16_rn(vs[j] - __bfloat162float(h));
    }
}

// ---------------- prep: transpose + split (weights) ----------------
__global__ __launch_bounds__(256) void transpose_split(const float* __restrict__ src,
                                                       __nv_bfloat16* __restrict__ dh,
                                                       __nv_bfloat16* __restrict__ dl,
                                                       int R, int C) {
    __shared__ float tile[32][33];
    int c0 = blockIdx.x * 32, r0 = blockIdx.y * 32;
    int tx = threadIdx.x & 31, ty = threadIdx.x >> 5;
#pragma unroll
    for (int i = 0; i < 4; i++)
        tile[ty + 8*i][tx] = src[(size_t)(r0 + ty + 8*i) * C + c0 + tx];
    __syncthreads();
#pragma unroll
    for (int i = 0; i < 4; i++) {
        float v = tile[tx][ty + 8*i];
        __nv_bfloat16 h = __float2bfloat16_rn(v);
        size_t o = (size_t)(c0 + ty + 8*i) * R + r0 + tx;
        dh[o] = h;
        dl[o] = __float2bfloat16_rn(v - __bfloat162float(h));
    }
}

// ---------------- prep: split qkv to head-major bf16 (+ k layernorm) ----------------
__global__ __launch_bounds__(256) void split_qkv() {
    __shared__ float vt[64][65];
    int bid = blockIdx.x;
    int lt = bid & 15;
    int bh = bid >> 4;
    int h = bh & 15, b = bh >> 4;
    int t = threadIdx.x;
    int lr = t >> 2, dk0 = (t & 3) * 16;
    int l = lt * 64 + lr;
    size_t base = (size_t)(b*Lq + l) * 3072 + h*64 + dk0;

    float q[16], k[16], v[16];
#pragma unroll
    for (int j = 0; j < 4; j++) {
        *(float4*)&q[4*j] = *(const float4*)&g_qkv[base + 4*j];
        *(float4*)&k[4*j] = *(const float4*)&g_qkv[base + 1024 + 4*j];
        *(float4*)&v[4*j] = *(const float4*)&g_qkv[base + 2048 + 4*j];
    }
    float s = 0.f, ss = 0.f;
#pragma unroll
    for (int j = 0; j < 16; j++) { s += k[j]; ss += k[j]*k[j]; }
    s  += __shfl_xor_sync(0xffffffffu, s, 1);  s  += __shfl_xor_sync(0xffffffffu, s, 2);
    ss += __shfl_xor_sync(0xffffffffu, ss, 1); ss += __shfl_xor_sync(0xffffffffu, ss, 2);
    float mu = s * (1.f/64.f);
    float var = ss * (1.f/64.f) - mu*mu;
    float rinv = rsqrtf(var + 1e-5f);
    size_t knb = (size_t)(b*Lq + l) * 1024 + h*64 + dk0;
#pragma unroll
    for (int j = 0; j < 4; j++) {
        float4 o = make_float4((k[4*j]-mu)*rinv, (k[4*j+1]-mu)*rinv,
                               (k[4*j+2]-mu)*rinv, (k[4*j+3]-mu)*rinv);
        *(float4*)&g_kn[knb + 4*j] = o;
    }
    size_t ob = ((size_t)bh*Lq + l) * 64 + dk0;
    uint32_t rh[8], rl[8];
    pack_split16(q, rh, rl);
    *(uint4*)&g_qh[ob] = *(uint4*)&rh[0]; *(uint4*)&g_qh[ob+8] = *(uint4*)&rh[4];
    *(uint4*)&g_ql[ob] = *(uint4*)&rl[0]; *(uint4*)&g_ql[ob+8] = *(uint4*)&rl[4];
    pack_split16(k, rh, rl);
    *(uint4*)&g_kh[ob] = *(uint4*)&rh[0]; *(uint4*)&g_kh[ob+8] = *(uint4*)&rh[4];
    *(uint4*)&g_kl[ob] = *(uint4*)&rl[0]; *(uint4*)&g_kl[ob+8] = *(uint4*)&rl[4];
#pragma unroll
    for (int j = 0; j < 16; j++) vt[dk0 + j][lr] = v[j];
    __syncthreads();
    int odk = t >> 2, l0 = (t & 3) * 16;
    float vv[16];
#pragma unroll
    for (int j = 0; j < 16; j++) vv[j] = vt[odk][l0 + j];
    pack_split16(vv, rh, rl);
    size_t vb = ((size_t)bh*64 + odk) * Lq + lt*64 + l0;
    *(uint4*)&g_vth[vb] = *(uint4*)&rh[0]; *(uint4*)&g_vth[vb+8] = *(uint4*)&rh[4];
    *(uint4*)&g_vtl[vb] = *(uint4*)&rl[0]; *(uint4*)&g_vtl[vb+8] = *(uint4*)&rl[4];
}

// ---------------- bf16 split-GEMM (R8 structure): 128 threads, warp 64x64, 2-stage ----------------
#define GREG 9216
#define GST  36864
#define GEMM_SMEM (2*GST)
__device__ __forceinline__ uint32_t uoff(uint32_t u) { return u*16u + ((u >> 3) << 4); }

__global__ __launch_bounds__(128) void gemm_bf16(const __nv_bfloat16* __restrict__ Ah,
                                                 const __nv_bfloat16* __restrict__ Al,
                                                 const __nv_bfloat16* __restrict__ Bh,
                                                 const __nv_bfloat16* __restrict__ Bl,
                                                 float* __restrict__ C,
                                                 int M, int N, int K) {
    extern __shared__ char sm[];
    uint32_t sb = smem_u32(sm);
    int t = threadIdx.x, wid = t >> 5, lane = t & 31;
    int bm = blockIdx.y * 128, bn = blockIdx.x * 128;
    int wm = wid >> 1, wn = wid & 1;

    const char* pA0 = (const char*)Ah;
    const char* pA1 = (const char*)Al;
    const char* pB0 = (const char*)Bh;
    const char* pB1 = (const char*)Bl;

    int a_row = (lane & 7) + ((lane >> 3) & 1) * 8;
    int a_kg  = lane >> 4;
    int b_mat = lane >> 3;
    int b_n   = ((b_mat >> 1) & 1) * 8 + (lane & 7);
    int b_kg  = b_mat & 1;
    uint32_t aoff[4][2], boff[4][2];
#pragma unroll
    for (int mt = 0; mt < 4; mt++)
#pragma unroll
        for (int g = 0; g < 2; g++)
            aoff[mt][g] = uoff((uint32_t)((wm*64 + mt*16 + a_row)*4 + g*2 + a_kg));
#pragma unroll
    for (int np = 0; np < 4; np++)
#pragma unroll
        for (int g = 0; g < 2; g++)
            boff[np][g] = uoff((uint32_t)((wn*64 + np*16 + b_n)*4 + g*2 + b_kg));

    float acc[4][8][4];
#pragma unroll
    for (int i = 0; i < 4; i++)
#pragma unroll
        for (int j = 0; j < 8; j++)
#pragma unroll
            for (int q = 0; q < 4; q++) acc[i][j][q] = 0.f;

    int nk = K >> 5;
#define G_ISSUE(st) do { \
    uint32_t bse = sb + ((st) & 1) * GST; \
    _Pragma("unroll") \
    for (int i = 0; i < 4; i++) { \
        uint32_t u = (uint32_t)(t + 128*i); \
        int row = u >> 2, kg = u & 3; \
        uint32_t sa = bse + uoff(u); \
        size_t gofs = ((size_t)(bm + row) * K + (st)*32 + kg*8) * 2; \
        size_t gofsB = ((size_t)(bn + row) * K + (st)*32 + kg*8) * 2; \
        cpa16(sa         , pA0 + gofs); \
        cpa16(sa + GREG  , pA1 + gofs); \
        cpa16(sa + 2*GREG, pB0 + gofsB); \
        cpa16(sa + 3*GREG, pB1 + gofsB); \
    } \
} while (0)
    G_ISSUE(0); CPA_COMMIT();

    for (int c = 0; c < nk; c++) {
        CPA_WAIT0();
        __syncthreads();
        if (c + 1 < nk) { G_ISSUE(c + 1); CPA_COMMIT(); }
        uint32_t stgb = sb + (c & 1) * GST;
#pragma unroll
        for (int g = 0; g < 2; g++) {
            uint32_t fah[4][4], fal[4][4];
#pragma unroll
            for (int mt = 0; mt < 4; mt++) {
                ldmx4(fah[mt], stgb +        aoff[mt][g]);
                ldmx4(fal[mt], stgb + GREG + aoff[mt][g]);
            }
#pragma unroll
            for (int np = 0; np < 4; np++) {
                uint32_t fbh[4], fbl[4];
                ldmx4(fbh, stgb + 2*GREG + boff[np][g]);
                ldmx4(fbl, stgb + 3*GREG + boff[np][g]);
#pragma unroll
                for (int mt = 0; mt < 4; mt++) {
                    mma16816(acc[mt][2*np],   fah[mt], fbh[0], fbh[1]);
                    mma16816(acc[mt][2*np+1], fah[mt], fbh[2], fbh[3]);
                }
#pragma unroll
                for (int mt = 0; mt < 4; mt++) {
                    mma16816(acc[mt][2*np],   fah[mt], fbl[0], fbl[1]);
                    mma16816(acc[mt][2*np+1], fah[mt], fbl[2], fbl[3]);
                }
#pragma unroll
                for (int mt = 0; mt < 4; mt++) {
                    mma16816(acc[mt][2*np],   fal[mt], fbh[0], fbh[1]);
                    mma16816(acc[mt][2*np+1], fal[mt], fbh[2], fbh[3]);
                }
            }
        }
        __syncthreads();
    }
#undef G_ISSUE
    int rr = lane >> 2, cc = (lane & 3) * 2;
#pragma unroll
    for (int mt = 0; mt < 4; mt++)
#pragma unroll
        for (int nt = 0; nt < 8; nt++) {
            size_t r0 = (size_t)(bm + wm*64 + mt*16 + rr) * N + bn + wn*64 + nt*8 + cc;
            *(float2*)&C[r0]       = make_float2(acc[mt][nt][0], acc[mt][nt][1]);
            *(float2*)&C[r0 + 8*N] = make_float2(acc[mt][nt][2], acc[mt][nt][3]);
        }
}

// ---------------- merged kernel: attention (bid<256, pipelined) + passC recurrence (bid>=256) ----------------
#define RS 72
#define AQH 0
#define AQL 18432
#define AKV 36864
#define AKVST 36864
#define ATTN_SMEM (AKV + 4*AKVST)    /* 184320 */
__global__ __launch_bounds__(256) void attn_scan(const float* __restrict__ WL) {
    extern __shared__ char smc[];
    int bid = blockIdx.x;
    int t = threadIdx.x;

    if (bid < 256) {
        // ================= attention (software-pipelined S/softmax/PV) =================
        uint32_t sb = smem_u32(smc);
        int bh = bid & 31, b = bh >> 4, h = bh & 15;
        int q0 = (7 - (bid >> 5)) * 128;
        int wid = t >> 5, lane = t & 31;

        const char* Qhg = (const char*)(g_qh + (size_t)bh * Lq * 64);
        const char* Qlg = (const char*)(g_ql + (size_t)bh * Lq * 64);
        const char* Khg = (const char*)(g_kh + (size_t)bh * Lq * 64);
        const char* Klg = (const char*)(g_kl + (size_t)bh * Lq * 64);
        const char* Vhg = (const char*)(g_vth + (size_t)bh * 64 * Lq);
        const char* Vlg = (const char*)(g_vtl + (size_t)bh * 64 * Lq);

#pragma unroll
        for (int i = 0; i < 4; i++) {
            int unit = t + 256*i;
            int row = unit >> 3, un = unit & 7;
            uint32_t sa = sb + row*144 + un*16;
            size_t gb = (size_t)(q0 + row)*128 + un*16;
            cpa16(sa + AQH, Qhg + gb);
            cpa16(sa + AQL, Qlg + gb);
        }
#define KV_ISSUE(tile) do { \
    uint32_t stg = sb + AKV + ((tile) & 3) * AKVST; \
    int j0i = (tile) * 64; \
    _Pragma("unroll") \
    for (int i2 = 0; i2 < 2; i2++) { \
        int unit = t + 256*i2; \
        int row = unit >> 3, un = unit & 7; \
        uint32_t sa = stg + row*144 + un*16; \
        size_t gk = (size_t)(j0i + row)*128 + un*16; \
        size_t gv = (size_t)row*2048 + (size_t)j0i*2 + un*16; \
        cpa16(sa         , Khg + gk); \
        cpa16(sa +  9216 , Klg + gk); \
        cpa16(sa + 18432 , Vhg + gv); \
        cpa16(sa + 27648 , Vlg + gv); \
    } \
} while (0)
        KV_ISSUE(0); CPA_COMMIT();
        KV_ISSUE(1); CPA_COMMIT();
        KV_ISSUE(2); CPA_COMMIT();          // always in-bounds (j <= 191 < 1024)

        int a_row = (lane & 7) + ((lane >> 3) & 1) * 8;
        int a_kg  = lane >> 4;
        int b_mat = lane >> 3;
        int b_n   = ((b_mat >> 1) & 1) * 8 + (lane & 7);
        int b_kg  = b_mat & 1;
        uint32_t qh_addr[4], ql_addr[4];
#pragma unroll
        for (int ks = 0; ks < 4; ks++) {
            uint32_t off = (uint32_t)((wid*16 + a_row) * RS + ks*16 + a_kg*8) * 2;
            qh_addr[ks] = sb + AQH + off;
            ql_addr[ks] = sb + AQL + off;
        }
        int rl = wid*16 + (lane >> 2), rh2 = rl + 8;

        // S = Q K^T for one KV tile into s[8][4]
        auto compute_S = [&](float (*s)[4], uint32_t stg) {
#pragma unroll
            for (int nt = 0; nt < 8; nt++)
#pragma unroll
                for (int q = 0; q < 4; q++) s[nt][q] = 0.f;
#pragma unroll
            for (int ks = 0; ks < 4; ks++) {
                uint32_t ah[4], al[4];
                ldmx4(ah, qh_addr[ks]);
                ldmx4(al, ql_addr[ks]);
#pragma unroll
                for (int np = 0; np < 4; np++) {
                    uint32_t ko = (uint32_t)((np*16 + b_n) * RS + ks*16 + b_kg*8) * 2;
                    uint32_t bh4[4], bl4[4];
                    ldmx4(bh4, stg + ko);
                    ldmx4(bl4, stg + 9216 + ko);
                    mma16816(s[np*2],   ah, bh4[0], bh4[1]);
                    mma16816(s[np*2+1], ah, bh4[2], bh4[3]);
                    mma16816(s[np*2],   ah, bl4[0], bl4[1]);
                    mma16816(s[np*2+1], ah, bl4[2], bl4[3]);
                    mma16816(s[np*2],   al, bh4[0], bh4[1]);
                    mma16816(s[np*2+1], al, bh4[2], bh4[3]);
                }
            }
        };

        float o[8][4];
#pragma unroll
        for (int nt = 0; nt < 8; nt++)
#pragma unroll
            for (int q = 0; q < 4; q++) o[nt][q] = 0.f;
        float mstL = -1e30f, lstL = 0.f, mstH = -1e30f, lstH = 0.f;   // row state in regs

        int ntiles = q0 / 64 + 2;
        float sA[8][4], sB[8][4];

        // prologue: group 0 (Q + KV0) ready, compute S(0)
        CPA_WAIT2();
        __syncthreads();
        compute_S(sA, sb + AKV + 0);

        for (int tile = 0; tile < ntiles; tile++) {
            int j0 = tile * 64;
            // ---- scale + causal mask on sA ----
#pragma unroll
            for (int nt = 0; nt < 8; nt++)
#pragma unroll
                for (int q = 0; q < 4; q++) sA[nt][q] *= 0.125f;
            if (tile >= ntiles - 2) {
                int qlo = q0 + rl, qhi = q0 + rh2;
#pragma unroll
                for (int nt = 0; nt < 8; nt++) {
                    int j = j0 + nt*8 + (lane & 3)*2;
                    if (j     > qlo) sA[nt][0] = -1e30f;
                    if (j + 1 > qlo) sA[nt][1] = -1e30f;
                    if (j     > qhi) sA[nt][2] = -1e30f;
                    if (j + 1 > qhi) sA[nt][3] = -1e30f;
                }
            }
            // ---- online softmax (register state, quad-uniform) ----
            float mlo = -1e30f, mhi = -1e30f;
#pragma unroll
            for (int nt = 0; nt < 8; nt++) {
                mlo = fmaxf(mlo, fmaxf(sA[nt][0], sA[nt][1]));
                mhi = fmaxf(mhi, fmaxf(sA[nt][2], sA[nt][3]));
            }
            mlo = fmaxf(mlo, __shfl_xor_sync(0xffffffffu, mlo, 1));
            mlo = fmaxf(mlo, __shfl_xor_sync(0xffffffffu, mlo, 2));
            mhi = fmaxf(mhi, __shfl_xor_sync(0xffffffffu, mhi, 1));
            mhi = fmaxf(mhi, __shfl_xor_sync(0xffffffffu, mhi, 2));
            float mtl = fmaxf(mstL, mlo), mth = fmaxf(mstH, mhi);
            float cl = __expf(mstL - mtl), ch = __expf(mstH - mth);
            float suml = 0.f, sumh = 0.f;
#pragma unroll
            for (int nt = 0; nt < 8; nt++) {
                sA[nt][0] = __expf(sA[nt][0] - mtl);
                sA[nt][1] = __expf(sA[nt][1] - mtl);
                sA[nt][2] = __expf(sA[nt][2] - mth);
                sA[nt][3] = __expf(sA[nt][3] - mth);
                suml += sA[nt][0] + sA[nt][1];
                sumh += sA[nt][2] + sA[nt][3];
            }
            suml += __shfl_xor_sync(0xffffffffu, suml, 1);
            suml += __shfl_xor_sync(0xffffffffu, suml, 2);
            sumh += __shfl_xor_sync(0xffffffffu, sumh, 1);
            sumh += __shfl_xor_sync(0xffffffffu, sumh, 2);
            mstL = mtl; lstL = lstL * cl + suml;
            mstH = mth; lstH = lstH * ch + sumh;
#pragma unroll
            for (int nt = 0; nt < 8; nt++) {
                o[nt][0] *= cl; o[nt][1] *= cl;
                o[nt][2] *= ch; o[nt][3] *= ch;
            }
            // ---- fetch next tile scores (overlaps softmax latency ahead of PV) ----
            bool more = (tile + 1 < ntiles);
            if (more) {
                CPA_WAIT1();                 // group tile+1 complete
                __syncthreads();             // + all warps past PV(tile-1)
                if (tile + 3 < ntiles) KV_ISSUE(tile + 3);
                CPA_COMMIT();
                compute_S(sB, sb + AKV + ((tile + 1) & 3) * AKVST);
            }
            // ---- PV(tile) ----
            uint32_t stg = sb + AKV + (tile & 3) * AKVST;
#pragma unroll
            for (int ks = 0; ks < 4; ks++) {
                float h00 = tobf_f(sA[2*ks][0]),   h01 = tobf_f(sA[2*ks][1]);
                float h02 = tobf_f(sA[2*ks][2]),   h03 = tobf_f(sA[2*ks][3]);
                float h10 = tobf_f(sA[2*ks+1][0]), h11 = tobf_f(sA[2*ks+1][1]);
                float h12 = tobf_f(sA[2*ks+1][2]), h13 = tobf_f(sA[2*ks+1][3]);
                uint32_t ph[4], pl[4];
                ph[0] = cvt2bf(h00, h01); ph[1] = cvt2bf(h02, h03);
                ph[2] = cvt2bf(h10, h11); ph[3] = cvt2bf(h12, h13);
                pl[0] = cvt2bf(sA[2*ks][0]-h00,   sA[2*ks][1]-h01);
                pl[1] = cvt2bf(sA[2*ks][2]-h02,   sA[2*ks][3]-h03);
                pl[2] = cvt2bf(sA[2*ks+1][0]-h10, sA[2*ks+1][1]-h11);
                pl[3] = cvt2bf(sA[2*ks+1][2]-h12, sA[2*ks+1][3]-h13);
#pragma unroll
                for (int np = 0; np < 4; np++) {
                    uint32_t vo = (uint32_t)((np*16 + b_n) * RS + ks*16 + b_kg*8) * 2;
                    uint32_t vh4[4], vl4[4];
                    ldmx4(vh4, stg + 18432 + vo);
                    ldmx4(vl4, stg + 27648 + vo);
                    mma16816(o[np*2],   ph, vh4[0], vh4[1]);
                    mma16816(o[np*2+1], ph, vh4[2], vh4[3]);
                    mma16816(o[np*2],   ph, vl4[0], vl4[1]);
                    mma16816(o[np*2+1], ph, vl4[2], vl4[3]);
                    mma16816(o[np*2],   pl, vh4[0], vh4[1]);
                    mma16816(o[np*2+1], pl, vh4[2], vh4[3]);
                }
            }
            if (more) {
#pragma unroll
                for (int nt = 0; nt < 8; nt++)
#pragma unroll
                    for (int q = 0; q < 4; q++) sA[nt][q] = sB[nt][q];
            }
        }
#undef KV_ISSUE
        float li = 1.f / lstL, lh = 1.f / lstH;
#pragma unroll
        for (int nt = 0; nt < 8; nt++) {
            size_t o0 = (size_t)(b*Lq + q0 + rl) * 1024 + h*64 + nt*8 + (lane & 3)*2;
            *(float2*)&g_so[o0]          = make_float2(o[nt][0]*li, o[nt][1]*li);
            *(float2*)&g_so[o0 + 8*1024] = make_float2(o[nt][2]*lh, o[nt][3]*lh);
        }
    } else {
        // ================= passC recurrence (writes g_ys; no g_so dependency) =================
        float* sk = (float*)smc;
        float* sv = sk + CHUNK*64;
        float* sq = sv + CHUNK*64;
        int pb = bid - 256;
        int c  = pb & (NC - 1);
        int bh = pb >> 3;
        int h  = bh & 15, b = bh >> 4;
        int d  = t >> 2, e0 = (t & 3) * 16;
        int pbase = h*4096 + d*64 + e0;
        u64 rr2[8], cf2[8], Wm2[8], F2[8];
#pragma unroll
        for (int j = 0; j < 8; j++) {
            rr2[j] = *(const u64*)&g_ret [pbase + 2*j];
            cf2[j] = *(const u64*)&g_coef[pbase + 2*j];
            Wm2[j] = *(const u64*)&WL    [pbase + 2*j];
            F2[j]  = *(const u64*)&g_Fin [(size_t)pb * 4096 + d*64 + e0 + 2*j];
        }
        int t0 = c * CHUNK;
        size_t kb = (size_t)(b*Lq + t0) * 1024 + h*64;
        size_t qb = (size_t)(b*Lq + t0) * 3072 + h*64;
        for (int idx = t; idx < 2048; idx += 256) {
            int s = idx >> 4, e4 = (idx & 15) * 4;
            *(float4*)&sk[s*64 + e4] = *(const float4*)&g_kn [kb + (size_t)s*1024 + e4];
            *(float4*)&sv[s*64 + e4] = *(const float4*)&g_qkv[qb + (size_t)s*3072 + 2048 + e4];
            *(float4*)&sq[s*64 + e4] = *(const float4*)&g_qkv[qb + (size_t)s*3072 + e4];
        }
        __syncthreads();
        bool lead = (t & 3) == 0;
        for (int s = 0; s < CHUNK; s++) {
            u64 vdd = dup2(sv[s*64 + d]);
            const u64* kp = (const u64*)&sk[s*64 + e0];
            const u64* qp = (const u64*)&sq[s*64 + e0];
            u64 y2 = 0ull;
#pragma unroll
            for (int j = 0; j < 8; j++) {
                u64 Fi = fma2(rr2[j], F2[j], mul2(mul2(cf2[j], vdd), kp[j]));
                F2[j] = Fi;
                y2 = fma2(add2(Wm2[j], Fi), qp[j], y2);
            }
            float ylo, yhi; upk2(y2, ylo, yhi);
            float y = ylo + yhi;
            y += __shfl_down_sync(0xffffffffu, y, 2);
            y += __shfl_down_sync(0xffffffffu, y, 1);
            if (lead) g_ys[kb + (size_t)s*1024 + d] = y;
        }
    }
}

// ---------------- gated mix + bf16 split of ymix ----------------
__global__ __launch_bounds__(256) void mix_split(const float* __restrict__ gate) {
    int i = blockIdx.x * 1024 + threadIdx.x * 4;
    int h = (i >> 6) & 15;
    float g = 1.f / (1.f + expf(-gate[h]));
    float4 so = *(const float4*)&g_so[i];
    float4 ys = *(const float4*)&g_ys[i];
    float m[4] = {g*so.x + (1.f-g)*ys.x, g*so.y + (1.f-g)*ys.y,
                  g*so.z + (1.f-g)*ys.z, g*so.w + (1.f-g)*ys.w};
#pragma unroll
    for (int j = 0; j < 4; j++) {
        __nv_bfloat16 hh = __float2bfloat16_rn(m[j]);
        g_ymh[i + j] = hh;
        g_yml[i + j] = __float2bfloat16_rn(m[j] - __bfloat162float(hh));
    }
}

// ---------------- STP physics precompute ----------------
__global__ void stp_param_kernel(const float* __restrict__ W,   const float* __restrict__ Vgs,
                                 const float* __restrict__ VT0, const float* __restrict__ btau,
                                 const float* __restrict__ bgm, const float* __restrict__ Cch,
                                 const float* __restrict__ gam, const float* __restrict__ alpha,
                                 const float* __restrict__ ICt) {
    int idx = blockIdx.x * 256 + threadIdx.x;
    if (idx >= Hq*DKq*DKq) return;
    int h = idx >> 12;
    float veff = Vgs[h] - VT0[h] + W[idx];
    float sp   = (veff > 20.f) ? veff : log1pf(expf(veff));
    float gch  = btau[h] * sp;
    float invc = 1.f / Cch[h];
    float sig  = 1.f / (1.f + expf(-veff));
    float G    = bgm[h] * sp * sig;
    float smk  = tanhf(alpha[0] * (gch - ICt[0]));
    g_ret[idx]  = expf(-gch * invc);
    g_retC[idx] = expf(-gch * invc * (float)CHUNK);
    g_coef[idx] = gam[h] * smk * G;
}

// ---------------- STP pass A (f32x2 packed) ----------------
#define PA_SMEM (2*CHUNK*64*4)
__global__ __launch_bounds__(256) void stp_passA() {
    extern __shared__ float sma[];
    float* sk = sma;
    float* sv = sma + CHUNK*64;
    int bid = blockIdx.x;
    int c  = bid & (NC - 1);
    int bh = bid >> 3;
    int h  = bh & 15, b = bh >> 4;
    int t  = threadIdx.x;
    int d  = t >> 2, e0 = (t & 3) * 16;
    int pbase = h*4096 + d*64 + e0;
    u64 rr2[8], cf2[8], Aa2[8];
#pragma unroll
    for (int j = 0; j < 8; j++) {
        rr2[j] = *(const u64*)&g_ret [pbase + 2*j];
        cf2[j] = *(const u64*)&g_coef[pbase + 2*j];
        Aa2[j] = 0ull;
    }
    int t0 = c * CHUNK;
    size_t kb = (size_t)(b*Lq + t0) * 1024 + h*64;
    size_t vb = (size_t)(b*Lq + t0) * 3072 + 2048 + h*64;
    for (int idx = t; idx < 2048; idx += 256) {
        int s = idx >> 4, e4 = (idx & 15) * 4;
        *(float4*)&sk[s*64 + e4] = *(const float4*)&g_kn [kb + (size_t)s*1024 + e4];
        *(float4*)&sv[s*64 + e4] = *(const float4*)&g_qkv[vb + (size_t)s*3072 + e4];
    }
    __syncthreads();
#pragma unroll 2
    for (int s = 0; s < CHUNK; s++) {
        u64 vdd = dup2(sv[s*64 + d]);
        const u64* kp = (const u64*)&sk[s*64 + e0];
#pragma unroll
        for (int j = 0; j < 8; j++)
            Aa2[j] = fma2(rr2[j], Aa2[j], mul2(mul2(cf2[j], vdd), kp[j]));
    }
    float* out = g_A + (size_t)bid * 4096 + d*64 + e0;
#pragma unroll
    for (int j = 0; j < 8; j++) {
        float lo, hi; upk2(Aa2[j], lo, hi);
        out[2*j] = lo; out[2*j+1] = hi;
    }
}

// ---------------- STP pass B ----------------
__global__ __launch_bounds__(256) void stp_passB() {
    int bh = blockIdx.x;
    int h  = bh & 15;
    int t  = threadIdx.x;
    int d = t >> 2, e0 = (t & 3) * 16;
    int pbase = h*4096 + d*64 + e0;
    float rc[16], F[16];
#pragma unroll
    for (int i = 0; i < 16; i++) { rc[i] = g_retC[pbase+i]; F[i] = 0.f; }
    size_t base = (size_t)bh * NC * 4096 + d*64 + e0;
    for (int c = 0; c < NC; c++) {
        float* fo = g_Fin + base + (size_t)c * 4096;
#pragma unroll
        for (int i = 0; i < 16; i++) fo[i] = F[i];
        if (c + 1 < NC) {
            const float* ai = g_A + base + (size_t)c * 4096;
#pragma unroll
            for (int i = 0; i < 16; i++) F[i] = fmaf(rc[i], F[i], ai[i]);
        }
    }
}

// ---------------- launch ----------------
extern "C" void kernel_launch(void* const* d_in, const int* in_sizes, int n_in,
                              void* d_out, int out_size) {
    const float* x     = (const float*)d_in[0];
    const float* Wqkv  = (const float*)d_in[1];
    const float* Wo    = (const float*)d_in[2];
    const float* WLTM  = (const float*)d_in[3];
    const float* Vgs   = (const float*)d_in[4];
    const float* VT0   = (const float*)d_in[5];
    const float* btau  = (const float*)d_in[6];
    const float* bgm   = (const float*)d_in[7];
    const float* Cch   = (const float*)d_in[8];
    const float* gam   = (const float*)d_in[9];
    const float* alpha = (const float*)d_in[10];
    const float* ICt   = (const float*)d_in[11];
    const float* gate  = (const float*)d_in[12];
    float* out = (float*)d_out;

    float *qkvp;
    __nv_bfloat16 *xh, *xl, *ymh, *yml, *wqh, *wql, *woh, *wol;
    cudaGetSymbolAddress((void**)&qkvp, g_qkv);
    cudaGetSymbolAddress((void**)&xh,  g_xh);
    cudaGetSymbolAddress((void**)&xl,  g_xl);
    cudaGetSymbolAddress((void**)&ymh, g_ymh);
    cudaGetSymbolAddress((void**)&yml, g_yml);
    cudaGetSymbolAddress((void**)&wqh, g_wqh);
    cudaGetSymbolAddress((void**)&wql, g_wql);
    cudaGetSymbolAddress((void**)&woh, g_woh);
    cudaGetSymbolAddress((void**)&wol, g_wol);
    cudaFuncSetAttribute(attn_scan, cudaFuncAttributeMaxDynamicSharedMemorySize, ATTN_SMEM);
    cudaFuncSetAttribute(gemm_bf16, cudaFuncAttributeMaxDynamicSharedMemorySize, GEMM_SMEM);
    cudaFuncSetAttribute(stp_passA, cudaFuncAttributeMaxDynamicSharedMemorySize, PA_SMEM);

    split_plain<<<2048, 256>>>(x, xh, xl, Bq*Lq*Dq);
    transpose_split<<<dim3(96, 32), 256>>>(Wqkv, wqh, wql, 1024, 3072);
    transpose_split<<<dim3(32, 32), 256>>>(Wo,   woh, wol, 1024, 1024);
    gemm_bf16<<<dim3(24, 16), 128, GEMM_SMEM>>>(xh, xl, wqh, wql, qkvp, 2048, 3072, 1024);
    split_qkv<<<512, 256>>>();
    stp_param_kernel<<<(Hq*DKq*DKq + 255)/256, 256>>>(WLTM, Vgs, VT0, btau, bgm, Cch, gam, alpha, ICt);
    stp_passA<<<Bq*Hq*NC, 256, PA_SMEM>>>();
    stp_passB<<<Bq*Hq, 256>>>();
    attn_scan<<<512, 256, ATTN_SMEM>>>(WLTM);          // pipelined attention ∪ passC recurrence
    mix_split<<<2048, 256>>>(gate);
    gemm_bf16<<<dim3(8, 16), 128, GEMM_SMEM>>>(ymh, yml, woh, wol, out, 2048, 1024, 1024);
}

// round 15
// speedup vs baseline: 1.0117x; 1.0117x over previous
#include <cuda_runtime.h>
#include <cuda_bf16.h>
#include <math.h>
#include <stdint.h>

#define Bq 2
#define Lq 1024
#define Dq 1024
#define Hq 16
#define DKq 64
#define CHUNK 128
#define NC (Lq/CHUNK)   /* 8 */

typedef unsigned long long u64;

// ---------------- helpers ----------------
__device__ __forceinline__ uint32_t smem_u32(const void* p) {
    uint32_t a;
    asm("{ .reg .u64 t; cvta.to.shared.u64 t, %1; cvt.u32.u64 %0, t; }" : "=r"(a) : "l"(p));
    return a;
}
__device__ __forceinline__ void ldmx4(uint32_t* r, uint32_t addr) {
    asm volatile("ldmatrix.sync.aligned.m8n8.x4.shared.b16 {%0,%1,%2,%3}, [%4];"
        : "=r"(r[0]), "=r"(r[1]), "=r"(r[2]), "=r"(r[3]) : "r"(addr));
}
__device__ __forceinline__ void mma16816(float* c, const uint32_t* a, uint32_t b0, uint32_t b1) {
    asm volatile("mma.sync.aligned.m16n8k16.row.col.f32.bf16.bf16.f32 "
        "{%0,%1,%2,%3}, {%4,%5,%6,%7}, {%8,%9}, {%0,%1,%2,%3};"
        : "+f"(c[0]), "+f"(c[1]), "+f"(c[2]), "+f"(c[3])
        : "r"(a[0]), "r"(a[1]), "r"(a[2]), "r"(a[3]), "r"(b0), "r"(b1));
}
__device__ __forceinline__ uint32_t cvt2bf(float lo, float hi) {
    uint32_t r;
    asm("cvt.rn.bf16x2.f32 %0, %1, %2;" : "=r"(r) : "f"(hi), "f"(lo));
    return r;
}
__device__ __forceinline__ float tobf_f(float v) {
    return __bfloat162float(__float2bfloat16_rn(v));
}
__device__ __forceinline__ void cpa16(uint32_t saddr, const void* g) {
    asm volatile("cp.async.ca.shared.global [%0], [%1], 16;" :: "r"(saddr), "l"(g));
}
#define CPA_COMMIT() asm volatile("cp.async.commit_group;" ::: "memory")
#define CPA_WAIT0()  asm volatile("cp.async.wait_group 0;" ::: "memory")

// f32x2 packed math
__device__ __forceinline__ u64 pk2(float lo, float hi) {
    u64 r; asm("mov.b64 %0, {%1, %2};" : "=l"(r) : "f"(lo), "f"(hi)); return r;
}
__device__ __forceinline__ u64 dup2(float v) { return pk2(v, v); }
__device__ __forceinline__ void upk2(u64 x, float& lo, float& hi) {
    asm("mov.b64 {%0, %1}, %2;" : "=f"(lo), "=f"(hi) : "l"(x));
}
__device__ __forceinline__ u64 fma2(u64 a, u64 b, u64 c) {
    u64 d; asm("fma.rn.f32x2 %0, %1, %2, %3;" : "=l"(d) : "l"(a), "l"(b), "l"(c)); return d;
}
__device__ __forceinline__ u64 mul2(u64 a, u64 b) {
    u64 d; asm("mul.rn.f32x2 %0, %1, %2;" : "=l"(d) : "l"(a), "l"(b)); return d;
}
__device__ __forceinline__ u64 add2(u64 a, u64 b) {
    u64 d; asm("add.rn.f32x2 %0, %1, %2;" : "=l"(d) : "l"(a), "l"(b)); return d;
}

// pack 16 floats -> 8 bf16x2 hi + 8 bf16x2 lo
__device__ __forceinline__ void pack_split16(const float* f, uint32_t* rh, uint32_t* rl) {
#pragma unroll
    for (int j = 0; j < 8; j++) {
        float a = f[2*j], b = f[2*j+1];
        uint32_t p = cvt2bf(a, b);
        float ah = __uint_as_float(p << 16);
        float bh = __uint_as_float(p & 0xffff0000u);
        rh[j] = p;
        rl[j] = cvt2bf(a - ah, b - bh);
    }
}

// ---------------- scratch ----------------
__device__ float g_qkv  [Bq*Lq*3*Dq];
__device__ float g_kn   [Bq*Lq*Dq];
__device__ float g_so   [Bq*Lq*Dq];
__device__ float g_ys   [Bq*Lq*Dq];
__device__ __nv_bfloat16 g_xh   [Bq*Lq*Dq];
__device__ __nv_bfloat16 g_xl   [Bq*Lq*Dq];
__device__ __nv_bfloat16 g_ymh  [Bq*Lq*Dq];
__device__ __nv_bfloat16 g_yml  [Bq*Lq*Dq];
__device__ __nv_bfloat16 g_wqh  [3*Dq*Dq];
__device__ __nv_bfloat16 g_wql  [3*Dq*Dq];
__device__ __nv_bfloat16 g_woh  [Dq*Dq];
__device__ __nv_bfloat16 g_wol  [Dq*Dq];
__device__ __nv_bfloat16 g_qh [Bq*Hq*Lq*DKq];
__device__ __nv_bfloat16 g_ql [Bq*Hq*Lq*DKq];
__device__ __nv_bfloat16 g_kh [Bq*Hq*Lq*DKq];
__device__ __nv_bfloat16 g_kl [Bq*Hq*Lq*DKq];
__device__ __nv_bfloat16 g_vth[Bq*Hq*DKq*Lq];
__device__ __nv_bfloat16 g_vtl[Bq*Hq*DKq*Lq];
__device__ float g_ret  [Hq*DKq*DKq];
__device__ float g_coef [Hq*DKq*DKq];
__device__ float g_retC [Hq*DKq*DKq];
__device__ float g_A    [Bq*Hq*NC*DKq*DKq];
__device__ float g_Fin  [Bq*Hq*NC*DKq*DKq];

// ---------------- prep: plain bf16 hi/lo split (for x) ----------------
__global__ __launch_bounds__(256) void split_plain(const float* __restrict__ s,
                                                   __nv_bfloat16* __restrict__ dh,
                                                   __nv_bfloat16* __restrict__ dl, int n) {
    int i = blockIdx.x * 1024 + threadIdx.x * 4;
    if (i >= n) return;
    float4 v = *(const float4*)&s[i];
    float vs[4] = {v.x, v.y, v.z, v.w};
#pragma unroll
    for (int j = 0; j < 4; j++) {
        __nv_bfloat16 h = __float2bfloat16_rn(vs[j]);
        dh[i + j] = h;
        dl[i + j] = __float2bfloat16_rn(vs[j] - __bfloat162float(h));
    }
}

// ---------------- prep: transpose + split (weights) ----------------
__global__ __launch_bounds__(256) void transpose_split(const float* __restrict__ src,
                                                       __nv_bfloat16* __restrict__ dh,
                                                       __nv_bfloat16* __restrict__ dl,
                                                       int R, int C) {
    __shared__ float tile[32][33];
    int c0 = blockIdx.x * 32, r0 = blockIdx.y * 32;
    int tx = threadIdx.x & 31, ty = threadIdx.x >> 5;
#pragma unroll
    for (int i = 0; i < 4; i++)
        tile[ty + 8*i][tx] = src[(size_t)(r0 + ty + 8*i) * C + c0 + tx];
    __syncthreads();
#pragma unroll
    for (int i = 0; i < 4; i++) {
        float v = tile[tx][ty + 8*i];
        __nv_bfloat16 h = __float2bfloat16_rn(v);
        size_t o = (size_t)(c0 + ty + 8*i) * R + r0 + tx;
        dh[o] = h;
        dl[o] = __float2bfloat16_rn(v - __bfloat162float(h));
    }
}

// ---------------- prep: split qkv to head-major bf16 (+ k layernorm) ----------------
__global__ __launch_bounds__(256) void split_qkv() {
    __shared__ float vt[64][65];
    int bid = blockIdx.x;
    int lt = bid & 15;
    int bh = bid >> 4;
    int h = bh & 15, b = bh >> 4;
    int t = threadIdx.x;
    int lr = t >> 2, dk0 = (t & 3) * 16;
    int l = lt * 64 + lr;
    size_t base = (size_t)(b*Lq + l) * 3072 + h*64 + dk0;

    float q[16], k[16], v[16];
#pragma unroll
    for (int j = 0; j < 4; j++) {
        *(float4*)&q[4*j] = *(const float4*)&g_qkv[base + 4*j];
        *(float4*)&k[4*j] = *(const float4*)&g_qkv[base + 1024 + 4*j];
        *(float4*)&v[4*j] = *(const float4*)&g_qkv[base + 2048 + 4*j];
    }
    float s = 0.f, ss = 0.f;
#pragma unroll
    for (int j = 0; j < 16; j++) { s += k[j]; ss += k[j]*k[j]; }
    s  += __shfl_xor_sync(0xffffffffu, s, 1);  s  += __shfl_xor_sync(0xffffffffu, s, 2);
    ss += __shfl_xor_sync(0xffffffffu, ss, 1); ss += __shfl_xor_sync(0xffffffffu, ss, 2);
    float mu = s * (1.f/64.f);
    float var = ss * (1.f/64.f) - mu*mu;
    float rinv = rsqrtf(var + 1e-5f);
    size_t knb = (size_t)(b*Lq + l) * 1024 + h*64 + dk0;
#pragma unroll
    for (int j = 0; j < 4; j++) {
        float4 o = make_float4((k[4*j]-mu)*rinv, (k[4*j+1]-mu)*rinv,
                               (k[4*j+2]-mu)*rinv, (k[4*j+3]-mu)*rinv);
        *(float4*)&g_kn[knb + 4*j] = o;
    }
    size_t ob = ((size_t)bh*Lq + l) * 64 + dk0;
    uint32_t rh[8], rl[8];
    pack_split16(q, rh, rl);
    *(uint4*)&g_qh[ob] = *(uint4*)&rh[0]; *(uint4*)&g_qh[ob+8] = *(uint4*)&rh[4];
    *(uint4*)&g_ql[ob] = *(uint4*)&rl[0]; *(uint4*)&g_ql[ob+8] = *(uint4*)&rl[4];
    pack_split16(k, rh, rl);
    *(uint4*)&g_kh[ob] = *(uint4*)&rh[0]; *(uint4*)&g_kh[ob+8] = *(uint4*)&rh[4];
    *(uint4*)&g_kl[ob] = *(uint4*)&rl[0]; *(uint4*)&g_kl[ob+8] = *(uint4*)&rl[4];
#pragma unroll
    for (int j = 0; j < 16; j++) vt[dk0 + j][lr] = v[j];
    __syncthreads();
    int odk = t >> 2, l0 = (t & 3) * 16;
    float vv[16];
#pragma unroll
    for (int j = 0; j < 16; j++) vv[j] = vt[odk][l0 + j];
    pack_split16(vv, rh, rl);
    size_t vb = ((size_t)bh*64 + odk) * Lq + lt*64 + l0;
    *(uint4*)&g_vth[vb] = *(uint4*)&rh[0]; *(uint4*)&g_vth[vb+8] = *(uint4*)&rh[4];
    *(uint4*)&g_vtl[vb] = *(uint4*)&rl[0]; *(uint4*)&g_vtl[vb+8] = *(uint4*)&rl[4];
}

// ---------------- bf16 split-GEMM (R8 structure): 128 threads, warp 64x64, 2-stage ----------------
#define GREG 9216
#define GST  36864
#define GEMM_SMEM (2*GST)
__device__ __forceinline__ uint32_t uoff(uint32_t u) { return u*16u + ((u >> 3) << 4); }

__global__ __launch_bounds__(128) void gemm_bf16(const __nv_bfloat16* __restrict__ Ah,
                                                 const __nv_bfloat16* __restrict__ Al,
                                                 const __nv_bfloat16* __restrict__ Bh,
                                                 const __nv_bfloat16* __restrict__ Bl,
                                                 float* __restrict__ C,
                                                 int M, int N, int K) {
    extern __shared__ char sm[];
    uint32_t sb = smem_u32(sm);
    int t = threadIdx.x, wid = t >> 5, lane = t & 31;
    int bm = blockIdx.y * 128, bn = blockIdx.x * 128;
    int wm = wid >> 1, wn = wid & 1;

    const char* pA0 = (const char*)Ah;
    const char* pA1 = (const char*)Al;
    const char* pB0 = (const char*)Bh;
    const char* pB1 = (const char*)Bl;

    int a_row = (lane & 7) + ((lane >> 3) & 1) * 8;
    int a_kg  = lane >> 4;
    int b_mat = lane >> 3;
    int b_n   = ((b_mat >> 1) & 1) * 8 + (lane & 7);
    int b_kg  = b_mat & 1;
    uint32_t aoff[4][2], boff[4][2];
#pragma unroll
    for (int mt = 0; mt < 4; mt++)
#pragma unroll
        for (int g = 0; g < 2; g++)
            aoff[mt][g] = uoff((uint32_t)((wm*64 + mt*16 + a_row)*4 + g*2 + a_kg));
#pragma unroll
    for (int np = 0; np < 4; np++)
#pragma unroll
        for (int g = 0; g < 2; g++)
            boff[np][g] = uoff((uint32_t)((wn*64 + np*16 + b_n)*4 + g*2 + b_kg));

    float acc[4][8][4];
#pragma unroll
    for (int i = 0; i < 4; i++)
#pragma unroll
        for (int j = 0; j < 8; j++)
#pragma unroll
            for (int q = 0; q < 4; q++) acc[i][j][q] = 0.f;

    int nk = K >> 5;
#define G_ISSUE(st) do { \
    uint32_t bse = sb + ((st) & 1) * GST; \
    _Pragma("unroll") \
    for (int i = 0; i < 4; i++) { \
        uint32_t u = (uint32_t)(t + 128*i); \
        int row = u >> 2, kg = u & 3; \
        uint32_t sa = bse + uoff(u); \
        size_t gofs = ((size_t)(bm + row) * K + (st)*32 + kg*8) * 2; \
        size_t gofsB = ((size_t)(bn + row) * K + (st)*32 + kg*8) * 2; \
        cpa16(sa         , pA0 + gofs); \
        cpa16(sa + GREG  , pA1 + gofs); \
        cpa16(sa + 2*GREG, pB0 + gofsB); \
        cpa16(sa + 3*GREG, pB1 + gofsB); \
    } \
} while (0)
    G_ISSUE(0); CPA_COMMIT();

    for (int c = 0; c < nk; c++) {
        CPA_WAIT0();
        __syncthreads();
        if (c + 1 < nk) { G_ISSUE(c + 1); CPA_COMMIT(); }
        uint32_t stgb = sb + (c & 1) * GST;
#pragma unroll
        for (int g = 0; g < 2; g++) {
            uint32_t fah[4][4], fal[4][4];
#pragma unroll
            for (int mt = 0; mt < 4; mt++) {
                ldmx4(fah[mt], stgb +        aoff[mt][g]);
                ldmx4(fal[mt], stgb + GREG + aoff[mt][g]);
            }
#pragma unroll
            for (int np = 0; np < 4; np++) {
                uint32_t fbh[4], fbl[4];
                ldmx4(fbh, stgb + 2*GREG + boff[np][g]);
                ldmx4(fbl, stgb + 3*GREG + boff[np][g]);
#pragma unroll
                for (int mt = 0; mt < 4; mt++) {
                    mma16816(acc[mt][2*np],   fah[mt], fbh[0], fbh[1]);
                    mma16816(acc[mt][2*np+1], fah[mt], fbh[2], fbh[3]);
                }
#pragma unroll
                for (int mt = 0; mt < 4; mt++) {
                    mma16816(acc[mt][2*np],   fah[mt], fbl[0], fbl[1]);
                    mma16816(acc[mt][2*np+1], fah[mt], fbl[2], fbl[3]);
                }
#pragma unroll
                for (int mt = 0; mt < 4; mt++) {
                    mma16816(acc[mt][2*np],   fal[mt], fbh[0], fbh[1]);
                    mma16816(acc[mt][2*np+1], fal[mt], fbh[2], fbh[3]);
                }
            }
        }
        __syncthreads();
    }
#undef G_ISSUE
    int rr = lane >> 2, cc = (lane & 3) * 2;
#pragma unroll
    for (int mt = 0; mt < 4; mt++)
#pragma unroll
        for (int nt = 0; nt < 8; nt++) {
            size_t r0 = (size_t)(bm + wm*64 + mt*16 + rr) * N + bn + wn*64 + nt*8 + cc;
            *(float2*)&C[r0]       = make_float2(acc[mt][nt][0], acc[mt][nt][1]);
            *(float2*)&C[r0 + 8*N] = make_float2(acc[mt][nt][2], acc[mt][nt][3]);
        }
}

// ---------------- merged kernel: attention KT=128 (bid<256) + passC recurrence (bid>=256) ----------------
#define RS  72                     /* K/Q row stride elems (144B) */
#define RSV 136                    /* V row stride elems (272B)   */
#define AQH 0
#define AQL 18432
#define AKV 36864
#define KVKH 0
#define KVKL 18432
#define KVVH 36864
#define KVVL 54272
#define AKVST 71680
#define ATTN_SMEM (AKV + 2*AKVST)  /* 180224 */
__global__ __launch_bounds__(256) void attn_scan(const float* __restrict__ WL) {
    extern __shared__ char smc[];
    int bid = blockIdx.x;
    int t = threadIdx.x;

    if (bid < 256) {
        // ================= attention: 128-key tiles, 2-stage, 1 sync/tile =================
        uint32_t sb = smem_u32(smc);
        int bh = bid & 31, b = bh >> 4, h = bh & 15;
        int q0 = (7 - (bid >> 5)) * 128;     // heavy q-blocks first
        int wid = t >> 5, lane = t & 31;

        const char* Qhg = (const char*)(g_qh + (size_t)bh * Lq * 64);
        const char* Qlg = (const char*)(g_ql + (size_t)bh * Lq * 64);
        const char* Khg = (const char*)(g_kh + (size_t)bh * Lq * 64);
        const char* Klg = (const char*)(g_kl + (size_t)bh * Lq * 64);
        const char* Vhg = (const char*)(g_vth + (size_t)bh * 64 * Lq);
        const char* Vlg = (const char*)(g_vtl + (size_t)bh * 64 * Lq);

#pragma unroll
        for (int i = 0; i < 4; i++) {
            int unit = t + 256*i;
            int row = unit >> 3, un = unit & 7;
            uint32_t sa = sb + row*144 + un*16;
            size_t gb = (size_t)(q0 + row)*128 + un*16;
            cpa16(sa + AQH, Qhg + gb);
            cpa16(sa + AQL, Qlg + gb);
        }
        // KV tile = 128 keys: K 128x144B rows, V 64x272B rows
#define KV_ISSUE(tile) do { \
    uint32_t stg = sb + AKV + ((tile) & 1) * AKVST; \
    int j0i = (tile) * 128; \
    _Pragma("unroll") \
    for (int i2 = 0; i2 < 4; i2++) { \
        int uk = t + 256*i2; \
        int krow = uk >> 3, kun = uk & 7; \
        uint32_t ksa = stg + krow*144 + kun*16; \
        size_t gk = (size_t)(j0i + krow)*128 + kun*16; \
        cpa16(ksa + KVKH, Khg + gk); \
        cpa16(ksa + KVKL, Klg + gk); \
        int vrow = uk >> 4, vun = uk & 15; \
        uint32_t vsa = stg + vrow*272 + vun*16; \
        size_t gv = (size_t)vrow*2048 + (size_t)j0i*2 + vun*16; \
        cpa16(vsa + KVVH, Vhg + gv); \
        cpa16(vsa + KVVL, Vlg + gv); \
    } \
} while (0)
        KV_ISSUE(0);
        CPA_COMMIT();

        int a_row = (lane & 7) + ((lane >> 3) & 1) * 8;
        int a_kg  = lane >> 4;
        int b_mat = lane >> 3;
        int b_n   = ((b_mat >> 1) & 1) * 8 + (lane & 7);
        int b_kg  = b_mat & 1;
        uint32_t qh_addr[4], ql_addr[4];
#pragma unroll
        for (int ks = 0; ks < 4; ks++) {
            uint32_t off = (uint32_t)((wid*16 + a_row) * RS + ks*16 + a_kg*8) * 2;
            qh_addr[ks] = sb + AQH + off;
            ql_addr[ks] = sb + AQL + off;
        }
        int rl = wid*16 + (lane >> 2), rh2 = rl + 8;

        float o[8][4];
#pragma unroll
        for (int nt = 0; nt < 8; nt++)
#pragma unroll
            for (int q = 0; q < 4; q++) o[nt][q] = 0.f;
        float mstL = -1e30f, lstL = 0.f, mstH = -1e30f, lstH = 0.f;

        int ntiles = q0 / 128 + 1;
        for (int tile = 0; tile < ntiles; tile++) {
            int j0 = tile * 128;
            CPA_WAIT0();
            __syncthreads();                     // stage `tile` ready; prev compute done
            if (tile + 1 < ntiles) { KV_ISSUE(tile + 1); CPA_COMMIT(); }
            uint32_t stg = sb + AKV + (tile & 1) * AKVST;

            // ---- S = Q K^T over 128 keys ----
            float s[16][4];
#pragma unroll
            for (int nt = 0; nt < 16; nt++)
#pragma unroll
                for (int q = 0; q < 4; q++) s[nt][q] = 0.f;
#pragma unroll
            for (int ks = 0; ks < 4; ks++) {
                uint32_t ah[4], al[4];
                ldmx4(ah, qh_addr[ks]);
                ldmx4(al, ql_addr[ks]);
#pragma unroll
                for (int np = 0; np < 8; np++) {
                    uint32_t ko = (uint32_t)((np*16 + b_n) * RS + ks*16 + b_kg*8) * 2;
                    uint32_t bh4[4], bl4[4];
                    ldmx4(bh4, stg + KVKH + ko);
                    ldmx4(bl4, stg + KVKL + ko);
                    mma16816(s[np*2],   ah, bh4[0], bh4[1]);
                    mma16816(s[np*2+1], ah, bh4[2], bh4[3]);
                    mma16816(s[np*2],   ah, bl4[0], bl4[1]);
                    mma16816(s[np*2+1], ah, bl4[2], bl4[3]);
                    mma16816(s[np*2],   al, bh4[0], bh4[1]);
                    mma16816(s[np*2+1], al, bh4[2], bh4[3]);
                }
            }
            // ---- scale + causal mask (diagonal tile only) ----
#pragma unroll
            for (int nt = 0; nt < 16; nt++)
#pragma unroll
                for (int q = 0; q < 4; q++) s[nt][q] *= 0.125f;
            if (tile == ntiles - 1) {
                int qlo = q0 + rl, qhi = q0 + rh2;
#pragma unroll
                for (int nt = 0; nt < 16; nt++) {
                    int j = j0 + nt*8 + (lane & 3)*2;
                    if (j     > qlo) s[nt][0] = -1e30f;
                    if (j + 1 > qlo) s[nt][1] = -1e30f;
                    if (j     > qhi) s[nt][2] = -1e30f;
                    if (j + 1 > qhi) s[nt][3] = -1e30f;
                }
            }
            // ---- online softmax (register state) ----
            float mlo = -1e30f, mhi = -1e30f;
#pragma unroll
            for (int nt = 0; nt < 16; nt++) {
                mlo = fmaxf(mlo, fmaxf(s[nt][0], s[nt][1]));
                mhi = fmaxf(mhi, fmaxf(s[nt][2], s[nt][3]));
            }
            mlo = fmaxf(mlo, __shfl_xor_sync(0xffffffffu, mlo, 1));
            mlo = fmaxf(mlo, __shfl_xor_sync(0xffffffffu, mlo, 2));
            mhi = fmaxf(mhi, __shfl_xor_sync(0xffffffffu, mhi, 1));
            mhi = fmaxf(mhi, __shfl_xor_sync(0xffffffffu, mhi, 2));
            float mtl = fmaxf(mstL, mlo), mth = fmaxf(mstH, mhi);
            float cl = __expf(mstL - mtl), ch = __expf(mstH - mth);
            float suml = 0.f, sumh = 0.f;
#pragma unroll
            for (int nt = 0; nt < 16; nt++) {
                s[nt][0] = __expf(s[nt][0] - mtl);
                s[nt][1] = __expf(s[nt][1] - mtl);
                s[nt][2] = __expf(s[nt][2] - mth);
                s[nt][3] = __expf(s[nt][3] - mth);
                suml += s[nt][0] + s[nt][1];
                sumh += s[nt][2] + s[nt][3];
            }
            suml += __shfl_xor_sync(0xffffffffu, suml, 1);
            suml += __shfl_xor_sync(0xffffffffu, suml, 2);
            sumh += __shfl_xor_sync(0xffffffffu, sumh, 1);
            sumh += __shfl_xor_sync(0xffffffffu, sumh, 2);
            mstL = mtl; lstL = lstL * cl + suml;
            mstH = mth; lstH = lstH * ch + sumh;
#pragma unroll
            for (int nt = 0; nt < 8; nt++) {
                o[nt][0] *= cl; o[nt][1] *= cl;
                o[nt][2] *= ch; o[nt][3] *= ch;
            }
            // ---- PV over 128 keys ----
#pragma unroll
            for (int ks2 = 0; ks2 < 8; ks2++) {
                float h00 = tobf_f(s[2*ks2][0]),   h01 = tobf_f(s[2*ks2][1]);
                float h02 = tobf_f(s[2*ks2][2]),   h03 = tobf_f(s[2*ks2][3]);
                float h10 = tobf_f(s[2*ks2+1][0]), h11 = tobf_f(s[2*ks2+1][1]);
                float h12 = tobf_f(s[2*ks2+1][2]), h13 = tobf_f(s[2*ks2+1][3]);
                uint32_t ph[4], pl[4];
                ph[0] = cvt2bf(h00, h01); ph[1] = cvt2bf(h02, h03);
                ph[2] = cvt2bf(h10, h11); ph[3] = cvt2bf(h12, h13);
                pl[0] = cvt2bf(s[2*ks2][0]-h00,   s[2*ks2][1]-h01);
                pl[1] = cvt2bf(s[2*ks2][2]-h02,   s[2*ks2][3]-h03);
                pl[2] = cvt2bf(s[2*ks2+1][0]-h10, s[2*ks2+1][1]-h11);
                pl[3] = cvt2bf(s[2*ks2+1][2]-h12, s[2*ks2+1][3]-h13);
#pragma unroll
                for (int np = 0; np < 4; np++) {
                    uint32_t vo = (uint32_t)((np*16 + b_n) * RSV + ks2*16 + b_kg*8) * 2;
                    uint32_t vh4[4], vl4[4];
                    ldmx4(vh4, stg + KVVH + vo);
                    ldmx4(vl4, stg + KVVL + vo);
                    mma16816(o[np*2],   ph, vh4[0], vh4[1]);
                    mma16816(o[np*2+1], ph, vh4[2], vh4[3]);
                    mma16816(o[np*2],   ph, vl4[0], vl4[1]);
                    mma16816(o[np*2+1], ph, vl4[2], vl4[3]);
                    mma16816(o[np*2],   pl, vh4[0], vh4[1]);
                    mma16816(o[np*2+1], pl, vh4[2], vh4[3]);
                }
            }
        }
#undef KV_ISSUE
        float li = 1.f / lstL, lh = 1.f / lstH;
#pragma unroll
        for (int nt = 0; nt < 8; nt++) {
            size_t o0 = (size_t)(b*Lq + q0 + rl) * 1024 + h*64 + nt*8 + (lane & 3)*2;
            *(float2*)&g_so[o0]          = make_float2(o[nt][0]*li, o[nt][1]*li);
            *(float2*)&g_so[o0 + 8*1024] = make_float2(o[nt][2]*lh, o[nt][3]*lh);
        }
    } else {
        // ================= passC recurrence (writes g_ys; no g_so dependency) =================
        float* sk = (float*)smc;
        float* sv = sk + CHUNK*64;
        float* sq = sv + CHUNK*64;
        int pb = bid - 256;
        int c  = pb & (NC - 1);
        int bh = pb >> 3;
        int h  = bh & 15, b = bh >> 4;
        int d  = t >> 2, e0 = (t & 3) * 16;
        int pbase = h*4096 + d*64 + e0;
        u64 rr2[8], cf2[8], Wm2[8], F2[8];
#pragma unroll
        for (int j = 0; j < 8; j++) {
            rr2[j] = *(const u64*)&g_ret [pbase + 2*j];
            cf2[j] = *(const u64*)&g_coef[pbase + 2*j];
            Wm2[j] = *(const u64*)&WL    [pbase + 2*j];
            F2[j]  = *(const u64*)&g_Fin [(size_t)pb * 4096 + d*64 + e0 + 2*j];
        }
        int t0 = c * CHUNK;
        size_t kb = (size_t)(b*Lq + t0) * 1024 + h*64;
        size_t qb = (size_t)(b*Lq + t0) * 3072 + h*64;
        for (int idx = t; idx < 2048; idx += 256) {
            int s = idx >> 4, e4 = (idx & 15) * 4;
            *(float4*)&sk[s*64 + e4] = *(const float4*)&g_kn [kb + (size_t)s*1024 + e4];
            *(float4*)&sv[s*64 + e4] = *(const float4*)&g_qkv[qb + (size_t)s*3072 + 2048 + e4];
            *(float4*)&sq[s*64 + e4] = *(const float4*)&g_qkv[qb + (size_t)s*3072 + e4];
        }
        __syncthreads();
        bool lead = (t & 3) == 0;
        for (int s = 0; s < CHUNK; s++) {
            u64 vdd = dup2(sv[s*64 + d]);
            const u64* kp = (const u64*)&sk[s*64 + e0];
            const u64* qp = (const u64*)&sq[s*64 + e0];
            u64 y2 = 0ull;
#pragma unroll
            for (int j = 0; j < 8; j++) {
                u64 Fi = fma2(rr2[j], F2[j], mul2(mul2(cf2[j], vdd), kp[j]));
                F2[j] = Fi;
                y2 = fma2(add2(Wm2[j], Fi), qp[j], y2);
            }
            float ylo, yhi; upk2(y2, ylo, yhi);
            float y = ylo + yhi;
            y += __shfl_down_sync(0xffffffffu, y, 2);
            y += __shfl_down_sync(0xffffffffu, y, 1);
            if (lead) g_ys[kb + (size_t)s*1024 + d] = y;
        }
    }
}

// ---------------- gated mix + bf16 split of ymix ----------------
__global__ __launch_bounds__(256) void mix_split(const float* __restrict__ gate) {
    int i = blockIdx.x * 1024 + threadIdx.x * 4;
    int h = (i >> 6) & 15;
    float g = 1.f / (1.f + expf(-gate[h]));
    float4 so = *(const float4*)&g_so[i];
    float4 ys = *(const float4*)&g_ys[i];
    float m[4] = {g*so.x + (1.f-g)*ys.x, g*so.y + (1.f-g)*ys.y,
                  g*so.z + (1.f-g)*ys.z, g*so.w + (1.f-g)*ys.w};
#pragma unroll
    for (int j = 0; j < 4; j++) {
        __nv_bfloat16 hh = __float2bfloat16_rn(m[j]);
        g_ymh[i + j] = hh;
        g_yml[i + j] = __float2bfloat16_rn(m[j] - __bfloat162float(hh));
    }
}

// ---------------- STP physics precompute ----------------
__global__ void stp_param_kernel(const float* __restrict__ W,   const float* __restrict__ Vgs,
                                 const float* __restrict__ VT0, const float* __restrict__ btau,
                                 const float* __restrict__ bgm, const float* __restrict__ Cch,
                                 const float* __restrict__ gam, const float* __restrict__ alpha,
                                 const float* __restrict__ ICt) {
    int idx = blockIdx.x * 256 + threadIdx.x;
    if (idx >= Hq*DKq*DKq) return;
    int h = idx >> 12;
    float veff = Vgs[h] - VT0[h] + W[idx];
    float sp   = (veff > 20.f) ? veff : log1pf(expf(veff));
    float gch  = btau[h] * sp;
    float invc = 1.f / Cch[h];
    float sig  = 1.f / (1.f + expf(-veff));
    float G    = bgm[h] * sp * sig;
    float smk  = tanhf(alpha[0] * (gch - ICt[0]));
    g_ret[idx]  = expf(-gch * invc);
    g_retC[idx] = expf(-gch * invc * (float)CHUNK);
    g_coef[idx] = gam[h] * smk * G;
}

// ---------------- STP pass A (f32x2 packed) ----------------
#define PA_SMEM (2*CHUNK*64*4)
__global__ __launch_bounds__(256) void stp_passA() {
    extern __shared__ float sma[];
    float* sk = sma;
    float* sv = sma + CHUNK*64;
    int bid = blockIdx.x;
    int c  = bid & (NC - 1);
    int bh = bid >> 3;
    int h  = bh & 15, b = bh >> 4;
    int t  = threadIdx.x;
    int d  = t >> 2, e0 = (t & 3) * 16;
    int pbase = h*4096 + d*64 + e0;
    u64 rr2[8], cf2[8], Aa2[8];
#pragma unroll
    for (int j = 0; j < 8; j++) {
        rr2[j] = *(const u64*)&g_ret [pbase + 2*j];
        cf2[j] = *(const u64*)&g_coef[pbase + 2*j];
        Aa2[j] = 0ull;
    }
    int t0 = c * CHUNK;
    size_t kb = (size_t)(b*Lq + t0) * 1024 + h*64;
    size_t vb = (size_t)(b*Lq + t0) * 3072 + 2048 + h*64;
    for (int idx = t; idx < 2048; idx += 256) {
        int s = idx >> 4, e4 = (idx & 15) * 4;
        *(float4*)&sk[s*64 + e4] = *(const float4*)&g_kn [kb + (size_t)s*1024 + e4];
        *(float4*)&sv[s*64 + e4] = *(const float4*)&g_qkv[vb + (size_t)s*3072 + e4];
    }
    __syncthreads();
#pragma unroll 2
    for (int s = 0; s < CHUNK; s++) {
        u64 vdd = dup2(sv[s*64 + d]);
        const u64* kp = (const u64*)&sk[s*64 + e0];
#pragma unroll
        for (int j = 0; j < 8; j++)
            Aa2[j] = fma2(rr2[j], Aa2[j], mul2(mul2(cf2[j], vdd), kp[j]));
    }
    float* out = g_A + (size_t)bid * 4096 + d*64 + e0;
#pragma unroll
    for (int j = 0; j < 8; j++) {
        float lo, hi; upk2(Aa2[j], lo, hi);
        out[2*j] = lo; out[2*j+1] = hi;
    }
}

// ---------------- STP pass B ----------------
__global__ __launch_bounds__(256) void stp_passB() {
    int bh = blockIdx.x;
    int h  = bh & 15;
    int t  = threadIdx.x;
    int d = t >> 2, e0 = (t & 3) * 16;
    int pbase = h*4096 + d*64 + e0;
    float rc[16], F[16];
#pragma unroll
    for (int i = 0; i < 16; i++) { rc[i] = g_retC[pbase+i]; F[i] = 0.f; }
    size_t base = (size_t)bh * NC * 4096 + d*64 + e0;
    for (int c = 0; c < NC; c++) {
        float* fo = g_Fin + base + (size_t)c * 4096;
#pragma unroll
        for (int i = 0; i < 16; i++) fo[i] = F[i];
        if (c + 1 < NC) {
            const float* ai = g_A + base + (size_t)c * 4096;
#pragma unroll
            for (int i = 0; i < 16; i++) F[i] = fmaf(rc[i], F[i], ai[i]);
        }
    }
}

// ---------------- launch ----------------
extern "C" void kernel_launch(void* const* d_in, const int* in_sizes, int n_in,
                              void* d_out, int out_size) {
    const float* x     = (const float*)d_in[0];
    const float* Wqkv  = (const float*)d_in[1];
    const float* Wo    = (const float*)d_in[2];
    const float* WLTM  = (const float*)d_in[3];
    const float* Vgs   = (const float*)d_in[4];
    const float* VT0   = (const float*)d_in[5];
    const float* btau  = (const float*)d_in[6];
    const float* bgm   = (const float*)d_in[7];
    const float* Cch   = (const float*)d_in[8];
    const float* gam   = (const float*)d_in[9];
    const float* alpha = (const float*)d_in[10];
    const float* ICt   = (const float*)d_in[11];
    const float* gate  = (const float*)d_in[12];
    float* out = (float*)d_out;

    float *qkvp;
    __nv_bfloat16 *xh, *xl, *ymh, *yml, *wqh, *wql, *woh, *wol;
    cudaGetSymbolAddress((void**)&qkvp, g_qkv);
    cudaGetSymbolAddress((void**)&xh,  g_xh);
    cudaGetSymbolAddress((void**)&xl,  g_xl);
    cudaGetSymbolAddress((void**)&ymh, g_ymh);
    cudaGetSymbolAddress((void**)&yml, g_yml);
    cudaGetSymbolAddress((void**)&wqh, g_wqh);
    cudaGetSymbolAddress((void**)&wql, g_wql);
    cudaGetSymbolAddress((void**)&woh, g_woh);
    cudaGetSymbolAddress((void**)&wol, g_wol);
    cudaFuncSetAttribute(attn_scan, cudaFuncAttributeMaxDynamicSharedMemorySize, ATTN_SMEM);
    cudaFuncSetAttribute(gemm_bf16, cudaFuncAttributeMaxDynamicSharedMemorySize, GEMM_SMEM);
    cudaFuncSetAttribute(stp_passA, cudaFuncAttributeMaxDynamicSharedMemorySize, PA_SMEM);

    split_plain<<<2048, 256>>>(x, xh, xl, Bq*Lq*Dq);
    transpose_split<<<dim3(96, 32), 256>>>(Wqkv, wqh, wql, 1024, 3072);
    transpose_split<<<dim3(32, 32), 256>>>(Wo,   woh, wol, 1024, 1024);
    gemm_bf16<<<dim3(24, 16), 128, GEMM_SMEM>>>(xh, xl, wqh, wql, qkvp, 2048, 3072, 1024);
    split_qkv<<<512, 256>>>();
    stp_param_kernel<<<(Hq*DKq*DKq + 255)/256, 256>>>(WLTM, Vgs, VT0, btau, bgm, Cch, gam, alpha, ICt);
    stp_passA<<<Bq*Hq*NC, 256, PA_SMEM>>>();
    stp_passB<<<Bq*Hq, 256>>>();
    attn_scan<<<512, 256, ATTN_SMEM>>>(WLTM);          // KT=128 attention ∪ passC recurrence
    mix_split<<<2048, 256>>>(gate);
    gemm_bf16<<<dim3(8, 16), 128, GEMM_SMEM>>>(ymh, yml, woh, wol, out, 2048, 1024, 1024);
}

// round 16
// speedup vs baseline: 1.0275x; 1.0156x over previous
#include <cuda_runtime.h>
#include <cuda_bf16.h>
#include <math.h>
#include <stdint.h>

#define Bq 2
#define Lq 1024
#define Dq 1024
#define Hq 16
#define DKq 64
#define CHUNK 128
#define NC (Lq/CHUNK)   /* 8 */

typedef unsigned long long u64;

// ---------------- helpers ----------------
__device__ __forceinline__ uint32_t smem_u32(const void* p) {
    uint32_t a;
    asm("{ .reg .u64 t; cvta.to.shared.u64 t, %1; cvt.u32.u64 %0, t; }" : "=r"(a) : "l"(p));
    return a;
}
__device__ __forceinline__ void ldmx4(uint32_t* r, uint32_t addr) {
    asm volatile("ldmatrix.sync.aligned.m8n8.x4.shared.b16 {%0,%1,%2,%3}, [%4];"
        : "=r"(r[0]), "=r"(r[1]), "=r"(r[2]), "=r"(r[3]) : "r"(addr));
}
__device__ __forceinline__ void mma16816(float* c, const uint32_t* a, uint32_t b0, uint32_t b1) {
    asm volatile("mma.sync.aligned.m16n8k16.row.col.f32.bf16.bf16.f32 "
        "{%0,%1,%2,%3}, {%4,%5,%6,%7}, {%8,%9}, {%0,%1,%2,%3};"
        : "+f"(c[0]), "+f"(c[1]), "+f"(c[2]), "+f"(c[3])
        : "r"(a[0]), "r"(a[1]), "r"(a[2]), "r"(a[3]), "r"(b0), "r"(b1));
}
__device__ __forceinline__ uint32_t cvt2bf(float lo, float hi) {
    uint32_t r;
    asm("cvt.rn.bf16x2.f32 %0, %1, %2;" : "=r"(r) : "f"(hi), "f"(lo));
    return r;
}
__device__ __forceinline__ float tobf_f(float v) {
    return __bfloat162float(__float2bfloat16_rn(v));
}
__device__ __forceinline__ void cpa16(uint32_t saddr, const void* g) {
    asm volatile("cp.async.ca.shared.global [%0], [%1], 16;" :: "r"(saddr), "l"(g));
}
#define CPA_COMMIT() asm volatile("cp.async.commit_group;" ::: "memory")
#define CPA_WAIT0()  asm volatile("cp.async.wait_group 0;" ::: "memory")

// f32x2 packed math
__device__ __forceinline__ u64 pk2(float lo, float hi) {
    u64 r; asm("mov.b64 %0, {%1, %2};" : "=l"(r) : "f"(lo), "f"(hi)); return r;
}
__device__ __forceinline__ u64 dup2(float v) { return pk2(v, v); }
__device__ __forceinline__ void upk2(u64 x, float& lo, float& hi) {
    asm("mov.b64 {%0, %1}, %2;" : "=f"(lo), "=f"(hi) : "l"(x));
}
__device__ __forceinline__ u64 fma2(u64 a, u64 b, u64 c) {
    u64 d; asm("fma.rn.f32x2 %0, %1, %2, %3;" : "=l"(d) : "l"(a), "l"(b), "l"(c)); return d;
}
__device__ __forceinline__ u64 mul2(u64 a, u64 b) {
    u64 d; asm("mul.rn.f32x2 %0, %1, %2;" : "=l"(d) : "l"(a), "l"(b)); return d;
}
__device__ __forceinline__ u64 add2(u64 a, u64 b) {
    u64 d; asm("add.rn.f32x2 %0, %1, %2;" : "=l"(d) : "l"(a), "l"(b)); return d;
}

// pack 16 floats -> 8 bf16x2 hi + 8 bf16x2 lo
__device__ __forceinline__ void pack_split16(const float* f, uint32_t* rh, uint32_t* rl) {
#pragma unroll
    for (int j = 0; j < 8; j++) {
        float a = f[2*j], b = f[2*j+1];
        uint32_t p = cvt2bf(a, b);
        float ah = __uint_as_float(p << 16);
        float bh = __uint_as_float(p & 0xffff0000u);
        rh[j] = p;
        rl[j] = cvt2bf(a - ah, b - bh);
    }
}

// ---------------- scratch ----------------
__device__ float g_qkv  [Bq*Lq*3*Dq];
__device__ float g_kn   [Bq*Lq*Dq];
__device__ float g_so   [Bq*Lq*Dq];
__device__ float g_ys   [Bq*Lq*Dq];
__device__ __nv_bfloat16 g_xh   [Bq*Lq*Dq];
__device__ __nv_bfloat16 g_xl   [Bq*Lq*Dq];
__device__ __nv_bfloat16 g_ymh  [Bq*Lq*Dq];
__device__ __nv_bfloat16 g_yml  [Bq*Lq*Dq];
__device__ __nv_bfloat16 g_wqh  [3*Dq*Dq];
__device__ __nv_bfloat16 g_wql  [3*Dq*Dq];
__device__ __nv_bfloat16 g_woh  [Dq*Dq];
__device__ __nv_bfloat16 g_wol  [Dq*Dq];
__device__ __nv_bfloat16 g_qh [Bq*Hq*Lq*DKq];
__device__ __nv_bfloat16 g_ql [Bq*Hq*Lq*DKq];
__device__ __nv_bfloat16 g_kh [Bq*Hq*Lq*DKq];
__device__ __nv_bfloat16 g_kl [Bq*Hq*Lq*DKq];
__device__ __nv_bfloat16 g_vth[Bq*Hq*DKq*Lq];
__device__ __nv_bfloat16 g_vtl[Bq*Hq*DKq*Lq];
__device__ float g_ret  [Hq*DKq*DKq];
__device__ float g_coef [Hq*DKq*DKq];
__device__ float g_retC [Hq*DKq*DKq];
__device__ float g_A    [Bq*Hq*NC*DKq*DKq];
__device__ float g_Fin  [Bq*Hq*NC*DKq*DKq];

// ---------------- prep: plain bf16 hi/lo split (for x) ----------------
__global__ __launch_bounds__(256) void split_plain(const float* __restrict__ s,
                                                   __nv_bfloat16* __restrict__ dh,
                                                   __nv_bfloat16* __restrict__ dl, int n) {
    int i = blockIdx.x * 1024 + threadIdx.x * 4;
    if (i >= n) return;
    float4 v = *(const float4*)&s[i];
    float vs[4] = {v.x, v.y, v.z, v.w};
#pragma unroll
    for (int j = 0; j < 4; j++) {
        __nv_bfloat16 h = __float2bfloat16_rn(vs[j]);
        dh[i + j] = h;
        dl[i + j] = __float2bfloat16_rn(vs[j] - __bfloat162float(h));
    }
}

// ---------------- prep: transpose + split (weights) ----------------
__global__ __launch_bounds__(256) void transpose_split(const float* __restrict__ src,
                                                       __nv_bfloat16* __restrict__ dh,
                                                       __nv_bfloat16* __restrict__ dl,
                                                       int R, int C) {
    __shared__ float tile[32][33];
    int c0 = blockIdx.x * 32, r0 = blockIdx.y * 32;
    int tx = threadIdx.x & 31, ty = threadIdx.x >> 5;
#pragma unroll
    for (int i = 0; i < 4; i++)
        tile[ty + 8*i][tx] = src[(size_t)(r0 + ty + 8*i) * C + c0 + tx];
    __syncthreads();
#pragma unroll
    for (int i = 0; i < 4; i++) {
        float v = tile[tx][ty + 8*i];
        __nv_bfloat16 h = __float2bfloat16_rn(v);
        size_t o = (size_t)(c0 + ty + 8*i) * R + r0 + tx;
        dh[o] = h;
        dl[o] = __float2bfloat16_rn(v - __bfloat162float(h));
    }
}

// ---------------- prep: split qkv to head-major bf16 (+ k layernorm) ----------------
__global__ __launch_bounds__(256) void split_qkv() {
    __shared__ float vt[64][65];
    int bid = blockIdx.x;
    int lt = bid & 15;
    int bh = bid >> 4;
    int h = bh & 15, b = bh >> 4;
    int t = threadIdx.x;
    int lr = t >> 2, dk0 = (t & 3) * 16;
    int l = lt * 64 + lr;
    size_t base = (size_t)(b*Lq + l) * 3072 + h*64 + dk0;

    float q[16], k[16], v[16];
#pragma unroll
    for (int j = 0; j < 4; j++) {
        *(float4*)&q[4*j] = *(const float4*)&g_qkv[base + 4*j];
        *(float4*)&k[4*j] = *(const float4*)&g_qkv[base + 1024 + 4*j];
        *(float4*)&v[4*j] = *(const float4*)&g_qkv[base + 2048 + 4*j];
    }
    float s = 0.f, ss = 0.f;
#pragma unroll
    for (int j = 0; j < 16; j++) { s += k[j]; ss += k[j]*k[j]; }
    s  += __shfl_xor_sync(0xffffffffu, s, 1);  s  += __shfl_xor_sync(0xffffffffu, s, 2);
    ss += __shfl_xor_sync(0xffffffffu, ss, 1); ss += __shfl_xor_sync(0xffffffffu, ss, 2);
    float mu = s * (1.f/64.f);
    float var = ss * (1.f/64.f) - mu*mu;
    float rinv = rsqrtf(var + 1e-5f);
    size_t knb = (size_t)(b*Lq + l) * 1024 + h*64 + dk0;
#pragma unroll
    for (int j = 0; j < 4; j++) {
        float4 o = make_float4((k[4*j]-mu)*rinv, (k[4*j+1]-mu)*rinv,
                               (k[4*j+2]-mu)*rinv, (k[4*j+3]-mu)*rinv);
        *(float4*)&g_kn[knb + 4*j] = o;
    }
    size_t ob = ((size_t)bh*Lq + l) * 64 + dk0;
    uint32_t rh[8], rl[8];
    pack_split16(q, rh, rl);
    *(uint4*)&g_qh[ob] = *(uint4*)&rh[0]; *(uint4*)&g_qh[ob+8] = *(uint4*)&rh[4];
    *(uint4*)&g_ql[ob] = *(uint4*)&rl[0]; *(uint4*)&g_ql[ob+8] = *(uint4*)&rl[4];
    pack_split16(k, rh, rl);
    *(uint4*)&g_kh[ob] = *(uint4*)&rh[0]; *(uint4*)&g_kh[ob+8] = *(uint4*)&rh[4];
    *(uint4*)&g_kl[ob] = *(uint4*)&rl[0]; *(uint4*)&g_kl[ob+8] = *(uint4*)&rl[4];
#pragma unroll
    for (int j = 0; j < 16; j++) vt[dk0 + j][lr] = v[j];
    __syncthreads();
    int odk = t >> 2, l0 = (t & 3) * 16;
    float vv[16];
#pragma unroll
    for (int j = 0; j < 16; j++) vv[j] = vt[odk][l0 + j];
    pack_split16(vv, rh, rl);
    size_t vb = ((size_t)bh*64 + odk) * Lq + lt*64 + l0;
    *(uint4*)&g_vth[vb] = *(uint4*)&rh[0]; *(uint4*)&g_vth[vb+8] = *(uint4*)&rh[4];
    *(uint4*)&g_vtl[vb] = *(uint4*)&rl[0]; *(uint4*)&g_vtl[vb+8] = *(uint4*)&rl[4];
}

// ---------------- bf16 split-GEMM (R8 structure): 128 threads, warp 64x64, 2-stage ----------------
#define GREG 9216
#define GST  36864
#define GEMM_SMEM (2*GST)
__device__ __forceinline__ uint32_t uoff(uint32_t u) { return u*16u + ((u >> 3) << 4); }

__global__ __launch_bounds__(128) void gemm_bf16(const __nv_bfloat16* __restrict__ Ah,
                                                 const __nv_bfloat16* __restrict__ Al,
                                                 const __nv_bfloat16* __restrict__ Bh,
                                                 const __nv_bfloat16* __restrict__ Bl,
                                                 float* __restrict__ C,
                                                 int M, int N, int K) {
    extern __shared__ char sm[];
    uint32_t sb = smem_u32(sm);
    int t = threadIdx.x, wid = t >> 5, lane = t & 31;
    int bm = blockIdx.y * 128, bn = blockIdx.x * 128;
    int wm = wid >> 1, wn = wid & 1;

    const char* pA0 = (const char*)Ah;
    const char* pA1 = (const char*)Al;
    const char* pB0 = (const char*)Bh;
    const char* pB1 = (const char*)Bl;

    int a_row = (lane & 7) + ((lane >> 3) & 1) * 8;
    int a_kg  = lane >> 4;
    int b_mat = lane >> 3;
    int b_n   = ((b_mat >> 1) & 1) * 8 + (lane & 7);
    int b_kg  = b_mat & 1;
    uint32_t aoff[4][2], boff[4][2];
#pragma unroll
    for (int mt = 0; mt < 4; mt++)
#pragma unroll
        for (int g = 0; g < 2; g++)
            aoff[mt][g] = uoff((uint32_t)((wm*64 + mt*16 + a_row)*4 + g*2 + a_kg));
#pragma unroll
    for (int np = 0; np < 4; np++)
#pragma unroll
        for (int g = 0; g < 2; g++)
            boff[np][g] = uoff((uint32_t)((wn*64 + np*16 + b_n)*4 + g*2 + b_kg));

    float acc[4][8][4];
#pragma unroll
    for (int i = 0; i < 4; i++)
#pragma unroll
        for (int j = 0; j < 8; j++)
#pragma unroll
            for (int q = 0; q < 4; q++) acc[i][j][q] = 0.f;

    int nk = K >> 5;
#define G_ISSUE(st) do { \
    uint32_t bse = sb + ((st) & 1) * GST; \
    _Pragma("unroll") \
    for (int i = 0; i < 4; i++) { \
        uint32_t u = (uint32_t)(t + 128*i); \
        int row = u >> 2, kg = u & 3; \
        uint32_t sa = bse + uoff(u); \
        size_t gofs = ((size_t)(bm + row) * K + (st)*32 + kg*8) * 2; \
        size_t gofsB = ((size_t)(bn + row) * K + (st)*32 + kg*8) * 2; \
        cpa16(sa         , pA0 + gofs); \
        cpa16(sa + GREG  , pA1 + gofs); \
        cpa16(sa + 2*GREG, pB0 + gofsB); \
        cpa16(sa + 3*GREG, pB1 + gofsB); \
    } \
} while (0)
    G_ISSUE(0); CPA_COMMIT();

    for (int c = 0; c < nk; c++) {
        CPA_WAIT0();
        __syncthreads();
        if (c + 1 < nk) { G_ISSUE(c + 1); CPA_COMMIT(); }
        uint32_t stgb = sb + (c & 1) * GST;
#pragma unroll
        for (int g = 0; g < 2; g++) {
            uint32_t fah[4][4], fal[4][4];
#pragma unroll
            for (int mt = 0; mt < 4; mt++) {
                ldmx4(fah[mt], stgb +        aoff[mt][g]);
                ldmx4(fal[mt], stgb + GREG + aoff[mt][g]);
            }
#pragma unroll
            for (int np = 0; np < 4; np++) {
                uint32_t fbh[4], fbl[4];
                ldmx4(fbh, stgb + 2*GREG + boff[np][g]);
                ldmx4(fbl, stgb + 3*GREG + boff[np][g]);
#pragma unroll
                for (int mt = 0; mt < 4; mt++) {
                    mma16816(acc[mt][2*np],   fah[mt], fbh[0], fbh[1]);
                    mma16816(acc[mt][2*np+1], fah[mt], fbh[2], fbh[3]);
                }
#pragma unroll
                for (int mt = 0; mt < 4; mt++) {
                    mma16816(acc[mt][2*np],   fah[mt], fbl[0], fbl[1]);
                    mma16816(acc[mt][2*np+1], fah[mt], fbl[2], fbl[3]);
                }
#pragma unroll
                for (int mt = 0; mt < 4; mt++) {
                    mma16816(acc[mt][2*np],   fal[mt], fbh[0], fbh[1]);
                    mma16816(acc[mt][2*np+1], fal[mt], fbh[2], fbh[3]);
                }
            }
        }
        __syncthreads();
    }
#undef G_ISSUE
    int rr = lane >> 2, cc = (lane & 3) * 2;
#pragma unroll
    for (int mt = 0; mt < 4; mt++)
#pragma unroll
        for (int nt = 0; nt < 8; nt++) {
            size_t r0 = (size_t)(bm + wm*64 + mt*16 + rr) * N + bn + wn*64 + nt*8 + cc;
            *(float2*)&C[r0]       = make_float2(acc[mt][nt][0], acc[mt][nt][1]);
            *(float2*)&C[r0 + 8*N] = make_float2(acc[mt][nt][2], acc[mt][nt][3]);
        }
}

// ---------------- merged kernel: attention KT=128 reduced-precision (bid<256) + passC (bid>=256) ----------------
#define RS  72                     /* K/Q row stride elems (144B) */
#define RSV 136                    /* V row stride elems (272B)   */
#define AQH 0
#define AKV 18432
#define KVKH 0
#define KVKL 18432
#define KVVH 36864
#define KVVL 54272
#define AKVST 71680
#define ATTN_SMEM (AKV + 2*AKVST)  /* 161792 */
__global__ __launch_bounds__(256) void attn_scan(const float* __restrict__ WL) {
    extern __shared__ char smc[];
    int bid = blockIdx.x;
    int t = threadIdx.x;

    if (bid < 256) {
        // ================= attention: S = Qh(Kh+Kl), PV = Ph(Vh+Vl) =================
        uint32_t sb = smem_u32(smc);
        int bh = bid & 31, b = bh >> 4, h = bh & 15;
        int q0 = (7 - (bid >> 5)) * 128;     // heavy q-blocks first
        int wid = t >> 5, lane = t & 31;

        const char* Qhg = (const char*)(g_qh + (size_t)bh * Lq * 64);
        const char* Khg = (const char*)(g_kh + (size_t)bh * Lq * 64);
        const char* Klg = (const char*)(g_kl + (size_t)bh * Lq * 64);
        const char* Vhg = (const char*)(g_vth + (size_t)bh * 64 * Lq);
        const char* Vlg = (const char*)(g_vtl + (size_t)bh * 64 * Lq);

#pragma unroll
        for (int i = 0; i < 4; i++) {
            int unit = t + 256*i;
            int row = unit >> 3, un = unit & 7;
            uint32_t sa = sb + row*144 + un*16;
            size_t gb = (size_t)(q0 + row)*128 + un*16;
            cpa16(sa + AQH, Qhg + gb);
        }
        // KV tile = 128 keys: K hi/lo 128x144B rows, V hi/lo 64x272B rows
#define KV_ISSUE(tile) do { \
    uint32_t stg = sb + AKV + ((tile) & 1) * AKVST; \
    int j0i = (tile) * 128; \
    _Pragma("unroll") \
    for (int i2 = 0; i2 < 4; i2++) { \
        int uk = t + 256*i2; \
        int krow = uk >> 3, kun = uk & 7; \
        uint32_t ksa = stg + krow*144 + kun*16; \
        size_t gk = (size_t)(j0i + krow)*128 + kun*16; \
        cpa16(ksa + KVKH, Khg + gk); \
        cpa16(ksa + KVKL, Klg + gk); \
        int vrow = uk >> 4, vun = uk & 15; \
        uint32_t vsa = stg + vrow*272 + vun*16; \
        size_t gv = (size_t)vrow*2048 + (size_t)j0i*2 + vun*16; \
        cpa16(vsa + KVVH, Vhg + gv); \
        cpa16(vsa + KVVL, Vlg + gv); \
    } \
} while (0)
        KV_ISSUE(0);
        CPA_COMMIT();

        int a_row = (lane & 7) + ((lane >> 3) & 1) * 8;
        int a_kg  = lane >> 4;
        int b_mat = lane >> 3;
        int b_n   = ((b_mat >> 1) & 1) * 8 + (lane & 7);
        int b_kg  = b_mat & 1;
        uint32_t qh_addr[4];
#pragma unroll
        for (int ks = 0; ks < 4; ks++)
            qh_addr[ks] = sb + AQH + (uint32_t)((wid*16 + a_row) * RS + ks*16 + a_kg*8) * 2;
        int rl = wid*16 + (lane >> 2), rh2 = rl + 8;

        float o[8][4];
#pragma unroll
        for (int nt = 0; nt < 8; nt++)
#pragma unroll
            for (int q = 0; q < 4; q++) o[nt][q] = 0.f;
        float mstL = -1e30f, lstL = 0.f, mstH = -1e30f, lstH = 0.f;

        int ntiles = q0 / 128 + 1;
        for (int tile = 0; tile < ntiles; tile++) {
            int j0 = tile * 128;
            CPA_WAIT0();
            __syncthreads();
            if (tile + 1 < ntiles) { KV_ISSUE(tile + 1); CPA_COMMIT(); }
            uint32_t stg = sb + AKV + (tile & 1) * AKVST;

            // ---- S = Qh K^T (K split) over 128 keys ----
            float s[16][4];
#pragma unroll
            for (int nt = 0; nt < 16; nt++)
#pragma unroll
                for (int q = 0; q < 4; q++) s[nt][q] = 0.f;
#pragma unroll
            for (int ks = 0; ks < 4; ks++) {
                uint32_t ah[4];
                ldmx4(ah, qh_addr[ks]);
#pragma unroll
                for (int np = 0; np < 8; np++) {
                    uint32_t ko = (uint32_t)((np*16 + b_n) * RS + ks*16 + b_kg*8) * 2;
                    uint32_t bh4[4], bl4[4];
                    ldmx4(bh4, stg + KVKH + ko);
                    ldmx4(bl4, stg + KVKL + ko);
                    mma16816(s[np*2],   ah, bh4[0], bh4[1]);
                    mma16816(s[np*2+1], ah, bh4[2], bh4[3]);
                    mma16816(s[np*2],   ah, bl4[0], bl4[1]);
                    mma16816(s[np*2+1], ah, bl4[2], bl4[3]);
                }
            }
            // ---- scale + causal mask (diagonal tile only) ----
#pragma unroll
            for (int nt = 0; nt < 16; nt++)
#pragma unroll
                for (int q = 0; q < 4; q++) s[nt][q] *= 0.125f;
            if (tile == ntiles - 1) {
                int qlo = q0 + rl, qhi = q0 + rh2;
#pragma unroll
                for (int nt = 0; nt < 16; nt++) {
                    int j = j0 + nt*8 + (lane & 3)*2;
                    if (j     > qlo) s[nt][0] = -1e30f;
                    if (j + 1 > qlo) s[nt][1] = -1e30f;
                    if (j     > qhi) s[nt][2] = -1e30f;
                    if (j + 1 > qhi) s[nt][3] = -1e30f;
                }
            }
            // ---- online softmax (register state) ----
            float mlo = -1e30f, mhi = -1e30f;
#pragma unroll
            for (int nt = 0; nt < 16; nt++) {
                mlo = fmaxf(mlo, fmaxf(s[nt][0], s[nt][1]));
                mhi = fmaxf(mhi, fmaxf(s[nt][2], s[nt][3]));
            }
            mlo = fmaxf(mlo, __shfl_xor_sync(0xffffffffu, mlo, 1));
            mlo = fmaxf(mlo, __shfl_xor_sync(0xffffffffu, mlo, 2));
            mhi = fmaxf(mhi, __shfl_xor_sync(0xffffffffu, mhi, 1));
            mhi = fmaxf(mhi, __shfl_xor_sync(0xffffffffu, mhi, 2));
            float mtl = fmaxf(mstL, mlo), mth = fmaxf(mstH, mhi);
            float cl = __expf(mstL - mtl), ch = __expf(mstH - mth);
            float suml = 0.f, sumh = 0.f;
#pragma unroll
            for (int nt = 0; nt < 16; nt++) {
                s[nt][0] = __expf(s[nt][0] - mtl);
                s[nt][1] = __expf(s[nt][1] - mtl);
                s[nt][2] = __expf(s[nt][2] - mth);
                s[nt][3] = __expf(s[nt][3] - mth);
                suml += s[nt][0] + s[nt][1];
                sumh += s[nt][2] + s[nt][3];
            }
            suml += __shfl_xor_sync(0xffffffffu, suml, 1);
            suml += __shfl_xor_sync(0xffffffffu, suml, 2);
            sumh += __shfl_xor_sync(0xffffffffu, sumh, 1);
            sumh += __shfl_xor_sync(0xffffffffu, sumh, 2);
            mstL = mtl; lstL = lstL * cl + suml;
            mstH = mth; lstH = lstH * ch + sumh;
#pragma unroll
            for (int nt = 0; nt < 8; nt++) {
                o[nt][0] *= cl; o[nt][1] *= cl;
                o[nt][2] *= ch; o[nt][3] *= ch;
            }
            // ---- PV = Ph (Vh + Vl) over 128 keys ----
#pragma unroll
            for (int ks2 = 0; ks2 < 8; ks2++) {
                uint32_t ph[4];
                ph[0] = cvt2bf(s[2*ks2][0],   s[2*ks2][1]);
                ph[1] = cvt2bf(s[2*ks2][2],   s[2*ks2][3]);
                ph[2] = cvt2bf(s[2*ks2+1][0], s[2*ks2+1][1]);
                ph[3] = cvt2bf(s[2*ks2+1][2], s[2*ks2+1][3]);
#pragma unroll
                for (int np = 0; np < 4; np++) {
                    uint32_t vo = (uint32_t)((np*16 + b_n) * RSV + ks2*16 + b_kg*8) * 2;
                    uint32_t vh4[4], vl4[4];
                    ldmx4(vh4, stg + KVVH + vo);
                    ldmx4(vl4, stg + KVVL + vo);
                    mma16816(o[np*2],   ph, vh4[0], vh4[1]);
                    mma16816(o[np*2+1], ph, vh4[2], vh4[3]);
                    mma16816(o[np*2],   ph, vl4[0], vl4[1]);
                    mma16816(o[np*2+1], ph, vl4[2], vl4[3]);
                }
            }
        }
#undef KV_ISSUE
        float li = 1.f / lstL, lh = 1.f / lstH;
#pragma unroll
        for (int nt = 0; nt < 8; nt++) {
            size_t o0 = (size_t)(b*Lq + q0 + rl) * 1024 + h*64 + nt*8 + (lane & 3)*2;
            *(float2*)&g_so[o0]          = make_float2(o[nt][0]*li, o[nt][1]*li);
            *(float2*)&g_so[o0 + 8*1024] = make_float2(o[nt][2]*lh, o[nt][3]*lh);
        }
    } else {
        // ================= passC recurrence (writes g_ys; no g_so dependency) =================
        float* sk = (float*)smc;
        float* sv = sk + CHUNK*64;
        float* sq = sv + CHUNK*64;
        int pb = bid - 256;
        int c  = pb & (NC - 1);
        int bh = pb >> 3;
        int h  = bh & 15, b = bh >> 4;
        int d  = t >> 2, e0 = (t & 3) * 16;
        int pbase = h*4096 + d*64 + e0;
        u64 rr2[8], cf2[8], Wm2[8], F2[8];
#pragma unroll
        for (int j = 0; j < 8; j++) {
            rr2[j] = *(const u64*)&g_ret [pbase + 2*j];
            cf2[j] = *(const u64*)&g_coef[pbase + 2*j];
            Wm2[j] = *(const u64*)&WL    [pbase + 2*j];
            F2[j]  = *(const u64*)&g_Fin [(size_t)pb * 4096 + d*64 + e0 + 2*j];
        }
        int t0 = c * CHUNK;
        size_t kb = (size_t)(b*Lq + t0) * 1024 + h*64;
        size_t qb = (size_t)(b*Lq + t0) * 3072 + h*64;
        for (int idx = t; idx < 2048; idx += 256) {
            int s = idx >> 4, e4 = (idx & 15) * 4;
            *(float4*)&sk[s*64 + e4] = *(const float4*)&g_kn [kb + (size_t)s*1024 + e4];
            *(float4*)&sv[s*64 + e4] = *(const float4*)&g_qkv[qb + (size_t)s*3072 + 2048 + e4];
            *(float4*)&sq[s*64 + e4] = *(const float4*)&g_qkv[qb + (size_t)s*3072 + e4];
        }
        __syncthreads();
        bool lead = (t & 3) == 0;
        for (int s = 0; s < CHUNK; s++) {
            u64 vdd = dup2(sv[s*64 + d]);
            const u64* kp = (const u64*)&sk[s*64 + e0];
            const u64* qp = (const u64*)&sq[s*64 + e0];
            u64 y2 = 0ull;
#pragma unroll
            for (int j = 0; j < 8; j++) {
                u64 Fi = fma2(rr2[j], F2[j], mul2(mul2(cf2[j], vdd), kp[j]));
                F2[j] = Fi;
                y2 = fma2(add2(Wm2[j], Fi), qp[j], y2);
            }
            float ylo, yhi; upk2(y2, ylo, yhi);
            float y = ylo + yhi;
            y += __shfl_down_sync(0xffffffffu, y, 2);
            y += __shfl_down_sync(0xffffffffu, y, 1);
            if (lead) g_ys[kb + (size_t)s*1024 + d] = y;
        }
    }
}

// ---------------- gated mix + bf16 split of ymix ----------------
__global__ __launch_bounds__(256) void mix_split(const float* __restrict__ gate) {
    int i = blockIdx.x * 1024 + threadIdx.x * 4;
    int h = (i >> 6) & 15;
    float g = 1.f / (1.f + expf(-gate[h]));
    float4 so = *(const float4*)&g_so[i];
    float4 ys = *(const float4*)&g_ys[i];
    float m[4] = {g*so.x + (1.f-g)*ys.x, g*so.y + (1.f-g)*ys.y,
                  g*so.z + (1.f-g)*ys.z, g*so.w + (1.f-g)*ys.w};
#pragma unroll
    for (int j = 0; j < 4; j++) {
        __nv_bfloat16 hh = __float2bfloat16_rn(m[j]);
        g_ymh[i + j] = hh;
        g_yml[i + j] = __float2bfloat16_rn(m[j] - __bfloat162float(hh));
    }
}

// ---------------- STP physics precompute ----------------
__global__ void stp_param_kernel(const float* __restrict__ W,   const float* __restrict__ Vgs,
                                 const float* __restrict__ VT0, const float* __restrict__ btau,
                                 const float* __restrict__ bgm, const float* __restrict__ Cch,
                                 const float* __restrict__ gam, const float* __restrict__ alpha,
                                 const float* __restrict__ ICt) {
    int idx = blockIdx.x * 256 + threadIdx.x;
    if (idx >= Hq*DKq*DKq) return;
    int h = idx >> 12;
    float veff = Vgs[h] - VT0[h] + W[idx];
    float sp   = (veff > 20.f) ? veff : log1pf(expf(veff));
    float gch  = btau[h] * sp;
    float invc = 1.f / Cch[h];
    float sig  = 1.f / (1.f + expf(-veff));
    float G    = bgm[h] * sp * sig;
    float smk  = tanhf(alpha[0] * (gch - ICt[0]));
    g_ret[idx]  = expf(-gch * invc);
    g_retC[idx] = expf(-gch * invc * (float)CHUNK);
    g_coef[idx] = gam[h] * smk * G;
}

// ---------------- STP pass A (f32x2 packed) ----------------
#define PA_SMEM (2*CHUNK*64*4)
__global__ __launch_bounds__(256) void stp_passA() {
    extern __shared__ float sma[];
    float* sk = sma;
    float* sv = sma + CHUNK*64;
    int bid = blockIdx.x;
    int c  = bid & (NC - 1);
    int bh = bid >> 3;
    int h  = bh & 15, b = bh >> 4;
    int t  = threadIdx.x;
    int d  = t >> 2, e0 = (t & 3) * 16;
    int pbase = h*4096 + d*64 + e0;
    u64 rr2[8], cf2[8], Aa2[8];
#pragma unroll
    for (int j = 0; j < 8; j++) {
        rr2[j] = *(const u64*)&g_ret [pbase + 2*j];
        cf2[j] = *(const u64*)&g_coef[pbase + 2*j];
        Aa2[j] = 0ull;
    }
    int t0 = c * CHUNK;
    size_t kb = (size_t)(b*Lq + t0) * 1024 + h*64;
    size_t vb = (size_t)(b*Lq + t0) * 3072 + 2048 + h*64;
    for (int idx = t; idx < 2048; idx += 256) {
        int s = idx >> 4, e4 = (idx & 15) * 4;
        *(float4*)&sk[s*64 + e4] = *(const float4*)&g_kn [kb + (size_t)s*1024 + e4];
        *(float4*)&sv[s*64 + e4] = *(const float4*)&g_qkv[vb + (size_t)s*3072 + e4];
    }
    __syncthreads();
#pragma unroll 2
    for (int s = 0; s < CHUNK; s++) {
        u64 vdd = dup2(sv[s*64 + d]);
        const u64* kp = (const u64*)&sk[s*64 + e0];
#pragma unroll
        for (int j = 0; j < 8; j++)
            Aa2[j] = fma2(rr2[j], Aa2[j], mul2(mul2(cf2[j], vdd), kp[j]));
    }
    float* out = g_A + (size_t)bid * 4096 + d*64 + e0;
#pragma unroll
    for (int j = 0; j < 8; j++) {
        float lo, hi; upk2(Aa2[j], lo, hi);
        out[2*j] = lo; out[2*j+1] = hi;
    }
}

// ---------------- STP pass B ----------------
__global__ __launch_bounds__(256) void stp_passB() {
    int bh = blockIdx.x;
    int h  = bh & 15;
    int t  = threadIdx.x;
    int d = t >> 2, e0 = (t & 3) * 16;
    int pbase = h*4096 + d*64 + e0;
    float rc[16], F[16];
#pragma unroll
    for (int i = 0; i < 16; i++) { rc[i] = g_retC[pbase+i]; F[i] = 0.f; }
    size_t base = (size_t)bh * NC * 4096 + d*64 + e0;
    for (int c = 0; c < NC; c++) {
        float* fo = g_Fin + base + (size_t)c * 4096;
#pragma unroll
        for (int i = 0; i < 16; i++) fo[i] = F[i];
        if (c + 1 < NC) {
            const float* ai = g_A + base + (size_t)c * 4096;
#pragma unroll
            for (int i = 0; i < 16; i++) F[i] = fmaf(rc[i], F[i], ai[i]);
        }
    }
}

// ---------------- launch ----------------
extern "C" void kernel_launch(void* const* d_in, const int* in_sizes, int n_in,
                              void* d_out, int out_size) {
    const float* x     = (const float*)d_in[0];
    const float* Wqkv  = (const float*)d_in[1];
    const float* Wo    = (const float*)d_in[2];
    const float* WLTM  = (const float*)d_in[3];
    const float* Vgs   = (const float*)d_in[4];
    const float* VT0   = (const float*)d_in[5];
    const float* btau  = (const float*)d_in[6];
    const float* bgm   = (const float*)d_in[7];
    const float* Cch   = (const float*)d_in[8];
    const float* gam   = (const float*)d_in[9];
    const float* alpha = (const float*)d_in[10];
    const float* ICt   = (const float*)d_in[11];
    const float* gate  = (const float*)d_in[12];
    float* out = (float*)d_out;

    float *qkvp;
    __nv_bfloat16 *xh, *xl, *ymh, *yml, *wqh, *wql, *woh, *wol;
    cudaGetSymbolAddress((void**)&qkvp, g_qkv);
    cudaGetSymbolAddress((void**)&xh,  g_xh);
    cudaGetSymbolAddress((void**)&xl,  g_xl);
    cudaGetSymbolAddress((void**)&ymh, g_ymh);
    cudaGetSymbolAddress((void**)&yml, g_yml);
    cudaGetSymbolAddress((void**)&wqh, g_wqh);
    cudaGetSymbolAddress((void**)&wql, g_wql);
    cudaGetSymbolAddress((void**)&woh, g_woh);
    cudaGetSymbolAddress((void**)&wol, g_wol);
    cudaFuncSetAttribute(attn_scan, cudaFuncAttributeMaxDynamicSharedMemorySize, ATTN_SMEM);
    cudaFuncSetAttribute(gemm_bf16, cudaFuncAttributeMaxDynamicSharedMemorySize, GEMM_SMEM);
    cudaFuncSetAttribute(stp_passA, cudaFuncAttributeMaxDynamicSharedMemorySize, PA_SMEM);

    split_plain<<<2048, 256>>>(x, xh, xl, Bq*Lq*Dq);
    transpose_split<<<dim3(96, 32), 256>>>(Wqkv, wqh, wql, 1024, 3072);
    transpose_split<<<dim3(32, 32), 256>>>(Wo,   woh, wol, 1024, 1024);
    gemm_bf16<<<dim3(24, 16), 128, GEMM_SMEM>>>(xh, xl, wqh, wql, qkvp, 2048, 3072, 1024);
    split_qkv<<<512, 256>>>();
    stp_param_kernel<<<(Hq*DKq*DKq + 255)/256, 256>>>(WLTM, Vgs, VT0, btau, bgm, Cch, gam, alpha, ICt);
    stp_passA<<<Bq*Hq*NC, 256, PA_SMEM>>>();
    stp_passB<<<Bq*Hq, 256>>>();
    attn_scan<<<512, 256, ATTN_SMEM>>>(WLTM);          // reduced-precision attention ∪ passC
    mix_split<<<2048, 256>>>(gate);
    gemm_bf16<<<dim3(8, 16), 128, GEMM_SMEM>>>(ymh, yml, woh, wol, out, 2048, 1024, 1024);
}